// round 13
// baseline (speedup 1.0000x reference)
#include <cuda_runtime.h>
#include <cuda_fp16.h>
#include <math.h>
#include <stdint.h>

#define B_  32
#define N_  1024
#define C_  768
#define H_  12
#define D_  64
#define L_  128

// ---------------- scratch (device globals: no allocations allowed) ----------
__device__ __half g_xh [B_*N_*C_];      // x in fp16
__device__ __half g_Wqt[3*C_*C_];       // Wqkv^T  [2304][768] fp16
__device__ __half g_Wpt[C_*C_];         // Wproj^T [768][768] fp16
__device__ __half g_Qh [B_*N_*C_];      // Q projection, fp16
__device__ __half g_xph[B_*L_*C_];      // pooled tokens, fp16
__device__ __half g_KVh[B_*L_*2*C_];    // K|V projections, fp16
__device__ __half g_kfh[B_*H_*L_*D_];   // k_full fp16 [bh][128][64]
__device__ __half g_vth[B_*H_*D_*L_];   // v_full fp16 TRANSPOSED [bh][64][128]
__device__ __half g_ao [B_*N_*C_];      // attention output, fp16

__device__ __forceinline__ void mma_f16(
    float* c, uint32_t a0, uint32_t a1, uint32_t a2, uint32_t a3,
    uint32_t b0, uint32_t b1)
{
    asm volatile(
        "mma.sync.aligned.m16n8k16.row.col.f32.f16.f16.f32 "
        "{%0,%1,%2,%3}, {%4,%5,%6,%7}, {%8,%9}, {%0,%1,%2,%3};"
        : "+f"(c[0]), "+f"(c[1]), "+f"(c[2]), "+f"(c[3])
        : "r"(a0), "r"(a1), "r"(a2), "r"(a3), "r"(b0), "r"(b1));
}

__device__ __forceinline__ void ldsm4(uint32_t& r0, uint32_t& r1,
                                      uint32_t& r2, uint32_t& r3, uint32_t addr)
{
    asm volatile("ldmatrix.sync.aligned.m8n8.x4.shared.b16 {%0,%1,%2,%3}, [%4];"
                 : "=r"(r0), "=r"(r1), "=r"(r2), "=r"(r3) : "r"(addr));
}

__device__ __forceinline__ void cp16(uint32_t saddr, const void* g) {
    asm volatile("cp.async.ca.shared.global [%0], [%1], 16;"
                 :: "r"(saddr), "l"(g));
}

// ------- fused fp32->fp16 convert of x, plus pooled-token generation --------
__global__ void f2h_pool(const float* __restrict__ x, __half* __restrict__ xh,
                         __half* __restrict__ xp)
{
    long i = (long)blockIdx.x * blockDim.x + threadIdx.x;   // float4 index
    const long TOT4 = (long)B_*N_*C_/4;
    if (i >= TOT4) return;
    int c4  = (int)(i % (C_/4));
    int row = (int)((i / (C_/4)) % N_);
    int b   = (int)(i / ((long)(C_/4) * N_));
    float4 v = *reinterpret_cast<const float4*>(x + i*4);
    __half2 h0 = __float22half2_rn(make_float2(v.x, v.y));
    __half2 h1 = __float22half2_rn(make_float2(v.z, v.w));
    uint2 o;
    o.x = *reinterpret_cast<uint32_t*>(&h0);
    o.y = *reinterpret_cast<uint32_t*>(&h1);
    *reinterpret_cast<uint2*>(xh + i*4) = o;

    if (row < 2*L_ && !(row & 1)) {
        float4 w = *reinterpret_cast<const float4*>(x + i*4 + C_);
        __half2 p0 = __float22half2_rn(
            make_float2(0.5f*(v.x+w.x), 0.5f*(v.y+w.y)));
        __half2 p1 = __float22half2_rn(
            make_float2(0.5f*(v.z+w.z), 0.5f*(v.w+w.w)));
        uint2 q;
        q.x = *reinterpret_cast<uint32_t*>(&p0);
        q.y = *reinterpret_cast<uint32_t*>(&p1);
        long pi = ((long)b*L_ + (row >> 1)) * C_ + c4*4;
        *reinterpret_cast<uint2*>(xp + pi) = q;
    }
}

// ---------------- fp32 -> fp16 transpose: Wt[c][r] = W[r][c] ----------------
__global__ void f2h_T(const float* __restrict__ W, __half* __restrict__ Wt,
                      int rows, int cols)
{
    __shared__ float s[32][33];
    int c0 = blockIdx.x*32, r0 = blockIdx.y*32;
    int tx = threadIdx.x, ty = threadIdx.y;   // 32 x 8
    #pragma unroll
    for (int i = 0; i < 32; i += 8)
        s[ty+i][tx] = W[(long)(r0+ty+i)*cols + c0+tx];
    __syncthreads();
    #pragma unroll
    for (int i = 0; i < 32; i += 8)
        Wt[(long)(c0+ty+i)*rows + r0+tx] = __float2half_rn(s[tx][ty+i]);
}

// -------- fp16 GEMM, cp.async double-buffered, ldmatrix fragments -----------
#define TH_STR 40      // halves per smem row (32 data + 8 pad); 20 words

__global__ __launch_bounds__(256, 2) void hgemm(
    const __half* __restrict__ A, const __half* __restrict__ Bt,
    const float* __restrict__ bias, void* __restrict__ Cv,
    int K, int lda, int ldbt, int ldc, int half_out)
{
    __shared__ __half Ah[2][128*TH_STR];
    __shared__ __half Bh[2][128*TH_STR];

    const int t    = threadIdx.x;
    const int warp = t >> 5;
    const int lane = t & 31;
    const int group = lane >> 2;
    const int tid4  = lane & 3;
    const int wm = (warp & 1) * 64;
    const int wn = (warp >> 1) * 32;

    const int bm = blockIdx.y * 128, bn = blockIdx.x * 128;

    float acc[4][4][4];
    #pragma unroll
    for (int mf = 0; mf < 4; mf++)
        #pragma unroll
        for (int nf = 0; nf < 4; nf++)
            #pragma unroll
            for (int r = 0; r < 4; r++) acc[mf][nf][r] = 0.f;

    const uint32_t aB0 = (uint32_t)__cvta_generic_to_shared(&Ah[0][0]);
    const uint32_t aB1 = (uint32_t)__cvta_generic_to_shared(&Ah[1][0]);
    const uint32_t bB0 = (uint32_t)__cvta_generic_to_shared(&Bh[0][0]);
    const uint32_t bB1 = (uint32_t)__cvta_generic_to_shared(&Bh[1][0]);

    const int lane15 = lane & 15;
    const int lanehi = lane >> 4;
    uint32_t aOff[4];
    #pragma unroll
    for (int mf = 0; mf < 4; mf++)
        aOff[mf] = ((wm + mf*16 + lane15)*20 + lanehi*4)*4;
    const int bsel = lane >> 3;
    uint32_t bOff[2];
    #pragma unroll
    for (int pr = 0; pr < 2; pr++) {
        int row = wn + (pr*2 + (bsel>>1))*8 + (lane & 7);
        bOff[pr] = (row*20 + (bsel & 1)*4)*4;
    }

    const int ar0 = t >> 2,        aof = (t & 3) * 8;
    const int ar1 = ar0 + 64;
    const int br  = t >> 1,        bof = (t & 1) * 16;

    const int ns = K >> 5;

    cp16(aB0 + (ar0*TH_STR + aof)*2, A + (long)(bm + ar0)*lda + aof);
    cp16(aB0 + (ar1*TH_STR + aof)*2, A + (long)(bm + ar1)*lda + aof);
    cp16(bB0 + (br*TH_STR + bof)*2,     Bt + (long)(bn + br)*ldbt + bof);
    cp16(bB0 + (br*TH_STR + bof + 8)*2, Bt + (long)(bn + br)*ldbt + bof + 8);
    asm volatile("cp.async.commit_group;");

    for (int i = 0; i < ns; i++) {
        const int buf = i & 1;
        asm volatile("cp.async.wait_all;" ::: "memory");
        __syncthreads();

        if (i + 1 < ns) {
            const int kn = (i + 1) << 5;
            const uint32_t aB = buf ? aB0 : aB1;
            const uint32_t bB = buf ? bB0 : bB1;
            cp16(aB + (ar0*TH_STR + aof)*2, A + (long)(bm + ar0)*lda + kn + aof);
            cp16(aB + (ar1*TH_STR + aof)*2, A + (long)(bm + ar1)*lda + kn + aof);
            cp16(bB + (br*TH_STR + bof)*2,     Bt + (long)(bn + br)*ldbt + kn + bof);
            cp16(bB + (br*TH_STR + bof + 8)*2, Bt + (long)(bn + br)*ldbt + kn + bof + 8);
            asm volatile("cp.async.commit_group;");
        }

        const uint32_t aB = buf ? aB1 : aB0;
        const uint32_t bB = buf ? bB1 : bB0;

        #pragma unroll
        for (int ks = 0; ks < 2; ks++) {
            const uint32_t kwB = ks * 8 * 4;
            uint32_t a[4][4], b[4][2];
            #pragma unroll
            for (int mf = 0; mf < 4; mf++)
                ldsm4(a[mf][0], a[mf][1], a[mf][2], a[mf][3],
                      aB + aOff[mf] + kwB);
            ldsm4(b[0][0], b[0][1], b[1][0], b[1][1], bB + bOff[0] + kwB);
            ldsm4(b[2][0], b[2][1], b[3][0], b[3][1], bB + bOff[1] + kwB);
            #pragma unroll
            for (int mf = 0; mf < 4; mf++)
                #pragma unroll
                for (int nf = 0; nf < 4; nf++)
                    mma_f16(acc[mf][nf], a[mf][0], a[mf][1], a[mf][2], a[mf][3],
                            b[nf][0], b[nf][1]);
        }
    }

    if (half_out) {
        __half* C = reinterpret_cast<__half*>(Cv);
        #pragma unroll
        for (int mf = 0; mf < 4; mf++) {
            long r0 = bm + wm + mf*16 + group;
            #pragma unroll
            for (int nf = 0; nf < 4; nf++) {
                int c0 = bn + wn + nf*8 + tid4*2;
                float2 bi = *reinterpret_cast<const float2*>(bias + c0);
                __half2 h0 = __float22half2_rn(
                    make_float2(acc[mf][nf][0] + bi.x, acc[mf][nf][1] + bi.y));
                __half2 h1 = __float22half2_rn(
                    make_float2(acc[mf][nf][2] + bi.x, acc[mf][nf][3] + bi.y));
                *reinterpret_cast<__half2*>(C + r0*ldc + c0) = h0;
                *reinterpret_cast<__half2*>(C + (r0+8)*ldc + c0) = h1;
            }
        }
    } else {
        float* C = reinterpret_cast<float*>(Cv);
        #pragma unroll
        for (int mf = 0; mf < 4; mf++) {
            long r0 = bm + wm + mf*16 + group;
            #pragma unroll
            for (int nf = 0; nf < 4; nf++) {
                int c0 = bn + wn + nf*8 + tid4*2;
                float2 bi = *reinterpret_cast<const float2*>(bias + c0);
                float2 o0, o1;
                o0.x = acc[mf][nf][0] + bi.x; o0.y = acc[mf][nf][1] + bi.y;
                o1.x = acc[mf][nf][2] + bi.x; o1.y = acc[mf][nf][3] + bi.y;
                *reinterpret_cast<float2*>(C + r0*ldc + c0) = o0;
                *reinterpret_cast<float2*>(C + (r0+8)*ldc + c0) = o1;
            }
        }
    }
}

// ------ tensor-core kvcompress: out = E^T @ KV_head (64x64x128), + bank -----
__global__ __launch_bounds__(128) void kvcompress(
    const __half* __restrict__ KV, const float* __restrict__ E_k,
    const float* __restrict__ E_v, const float* __restrict__ k_bank,
    const float* __restrict__ v_bank, __half* __restrict__ kf,
    __half* __restrict__ vt)
{
    __shared__ __half Et[64*136];
    __shared__ __half Kt[64*136];

    const int which = blockIdx.x, h = blockIdx.y, b = blockIdx.z;
    const float* E    = which ? E_v : E_k;
    const float* bank = which ? v_bank : k_bank;

    const int t = threadIdx.x;
    const int warp = t >> 5, lane = t & 31;
    const int group = lane >> 2, tid4 = lane & 3;

    for (int i = t*4; i < 128*64; i += 512) {
        int s = i >> 6, c = i & 63;
        float4 v = *reinterpret_cast<const float4*>(E + s*64 + c);
        Et[(c+0)*136 + s] = __float2half_rn(v.x);
        Et[(c+1)*136 + s] = __float2half_rn(v.y);
        Et[(c+2)*136 + s] = __float2half_rn(v.z);
        Et[(c+3)*136 + s] = __float2half_rn(v.w);
    }
    const __half* kvp = KV + (long)b*L_*2*C_ + which*C_ + h*D_;
    for (int i = t*4; i < 128*64; i += 512) {
        int s = i >> 6, d = i & 63;
        uint2 raw = *reinterpret_cast<const uint2*>(kvp + (long)s*2*C_ + d);
        const __half* hp = reinterpret_cast<const __half*>(&raw);
        Kt[(d+0)*136 + s] = hp[0];
        Kt[(d+1)*136 + s] = hp[1];
        Kt[(d+2)*136 + s] = hp[2];
        Kt[(d+3)*136 + s] = hp[3];
    }
    __syncthreads();

    float acc[8][4];
    #pragma unroll
    for (int nf = 0; nf < 8; nf++)
        #pragma unroll
        for (int r = 0; r < 4; r++) acc[nf][r] = 0.f;

    const uint32_t* Ew = reinterpret_cast<const uint32_t*>(Et);
    const uint32_t* Kw = reinterpret_cast<const uint32_t*>(Kt);
    const int m0 = warp*16 + group;

    #pragma unroll
    for (int ks = 0; ks < 8; ks++) {
        const int kw = ks * 8;
        uint32_t a0 = Ew[(m0    )*68 + kw + tid4];
        uint32_t a1 = Ew[(m0 + 8)*68 + kw + tid4];
        uint32_t a2 = Ew[(m0    )*68 + kw + tid4 + 4];
        uint32_t a3 = Ew[(m0 + 8)*68 + kw + tid4 + 4];
        #pragma unroll
        for (int nf = 0; nf < 8; nf++) {
            uint32_t b0 = Kw[(nf*8+group)*68 + kw + tid4];
            uint32_t b1 = Kw[(nf*8+group)*68 + kw + tid4 + 4];
            mma_f16(acc[nf], a0, a1, a2, a3, b0, b1);
        }
    }

    const long bh = (long)(b*H_ + h);
    if (which == 0) {
        __half* out = kf + bh*L_*D_;
        #pragma unroll
        for (int nf = 0; nf < 8; nf++) {
            int d = nf*8 + tid4*2;
            __half2 h0 = __float22half2_rn(make_float2(acc[nf][0], acc[nf][1]));
            __half2 h1 = __float22half2_rn(make_float2(acc[nf][2], acc[nf][3]));
            *reinterpret_cast<__half2*>(out + (m0  )*64 + d) = h0;
            *reinterpret_cast<__half2*>(out + (m0+8)*64 + d) = h1;
        }
        __syncthreads();
        for (int i = t*4; i < 64*64; i += 512) {
            int r = i >> 6, d = i & 63;
            float4 v = *reinterpret_cast<const float4*>(
                bank + (long)b*64*C_ + (long)r*C_ + h*D_ + d);
            __half2 h0 = __float22half2_rn(make_float2(v.x, v.y));
            __half2 h1 = __float22half2_rn(make_float2(v.z, v.w));
            *reinterpret_cast<__half2*>(out + (64+r)*64 + d) = h0;
            *reinterpret_cast<__half2*>(out + (64+r)*64 + d + 2) = h1;
        }
    } else {
        __half* out = vt + bh*D_*L_;
        #pragma unroll
        for (int nf = 0; nf < 8; nf++) {
            int d = nf*8 + tid4*2;
            out[(d  )*128 + m0    ] = __float2half_rn(acc[nf][0]);
            out[(d+1)*128 + m0    ] = __float2half_rn(acc[nf][1]);
            out[(d  )*128 + m0 + 8] = __float2half_rn(acc[nf][2]);
            out[(d+1)*128 + m0 + 8] = __float2half_rn(acc[nf][3]);
        }
        __syncthreads();
        for (int i = t*4; i < 64*64; i += 512) {
            int r = i >> 6, d = i & 63;
            float4 v = *reinterpret_cast<const float4*>(
                bank + (long)b*64*C_ + (long)r*C_ + h*D_ + d);
            out[(d  )*128 + 64 + r] = __float2half_rn(v.x);
            out[(d+1)*128 + 64 + r] = __float2half_rn(v.y);
            out[(d+2)*128 + 64 + r] = __float2half_rn(v.z);
            out[(d+3)*128 + 64 + r] = __float2half_rn(v.w);
        }
    }
}

// -------- fp16 tensor-core attention, ldmatrix fragments --------------------
#define QS_W 36
#define VS_W 68
#define ATTN_SMEM ((128*QS_W + 64*VS_W + 128*VS_W + 128*QS_W) * 4)

__global__ __launch_bounds__(256, 2) void attn_tc(
    const __half* __restrict__ Q, const __half* __restrict__ kf,
    const __half* __restrict__ vt, __half* __restrict__ O)
{
    extern __shared__ uint32_t smu[];
    uint32_t* Ksw = smu;                      // [128][36]
    uint32_t* Vtw = Ksw + 128*QS_W;           // [64][68]
    uint32_t* Psw = Vtw + 64*VS_W;            // [128][68]
    uint32_t* Qsw = Psw + 128*VS_W;           // [128][36]

    const int t = threadIdx.x;
    const int warp = t >> 5, lane = t & 31;
    const int group = lane >> 2, tid4 = lane & 3;
    const int qb = blockIdx.x, h = blockIdx.y, b = blockIdx.z;

    const __half* kfp = kf + (long)(b*H_ + h) * L_ * D_;
    const __half* vtp = vt + (long)(b*H_ + h) * D_ * L_;

    for (int i = t*8; i < L_*D_; i += 2048) {
        int k = i >> 6, d = i & 63;
        *reinterpret_cast<uint4*>(&Ksw[k*QS_W + (d>>1)]) =
            *reinterpret_cast<const uint4*>(kfp + i);
    }
    for (int i = t*8; i < D_*L_; i += 2048) {
        int d = i >> 7, k = i & 127;
        *reinterpret_cast<uint4*>(&Vtw[d*VS_W + (k>>1)]) =
            *reinterpret_cast<const uint4*>(vtp + i);
    }
    {
        long base = ((long)b*N_ + qb*128) * C_ + h*D_;
        for (int i = t*8; i < 128*64; i += 2048) {
            int q = i >> 6, d = i & 63;
            *reinterpret_cast<uint4*>(&Qsw[q*QS_W + (d>>1)]) =
                *reinterpret_cast<const uint4*>(Q + base + (long)q*C_ + d);
        }
    }
    __syncthreads();

    const uint32_t kBase = (uint32_t)__cvta_generic_to_shared(Ksw);
    const uint32_t vBase = (uint32_t)__cvta_generic_to_shared(Vtw);
    const uint32_t pBase = (uint32_t)__cvta_generic_to_shared(Psw);
    const uint32_t qBase = (uint32_t)__cvta_generic_to_shared(Qsw);

    const int lane15 = lane & 15;
    const int lanehi = lane >> 4;
    const int bsel = lane >> 3;
    const int qrow = warp*16;

    float accS[16][4];
    #pragma unroll
    for (int nt = 0; nt < 16; nt++)
        #pragma unroll
        for (int r = 0; r < 4; r++) accS[nt][r] = 0.f;

    const uint32_t qOff = ((qrow + lane15)*QS_W + lanehi*4)*4;
    uint32_t kOff[8];
    #pragma unroll
    for (int pr = 0; pr < 8; pr++) {
        int krow = pr*16 + (bsel>>1)*8 + (lane & 7);
        kOff[pr] = (krow*QS_W + (bsel & 1)*4)*4;
    }

    #pragma unroll
    for (int ks = 0; ks < 4; ks++) {
        const uint32_t kwB = ks * 32;
        uint32_t a0, a1, a2, a3;
        ldsm4(a0, a1, a2, a3, qBase + qOff + kwB);
        #pragma unroll
        for (int pr = 0; pr < 8; pr++) {
            uint32_t b00, b01, b10, b11;
            ldsm4(b00, b01, b10, b11, kBase + kOff[pr] + kwB);
            mma_f16(accS[pr*2  ], a0, a1, a2, a3, b00, b01);
            mma_f16(accS[pr*2+1], a0, a1, a2, a3, b10, b11);
        }
    }

    const float scale = 0.125f;
    float m0 = -1e30f, m1 = -1e30f;
    #pragma unroll
    for (int nt = 0; nt < 16; nt++) {
        accS[nt][0] *= scale; accS[nt][1] *= scale;
        accS[nt][2] *= scale; accS[nt][3] *= scale;
        m0 = fmaxf(m0, fmaxf(accS[nt][0], accS[nt][1]));
        m1 = fmaxf(m1, fmaxf(accS[nt][2], accS[nt][3]));
    }
    m0 = fmaxf(m0, __shfl_xor_sync(0xffffffff, m0, 1));
    m0 = fmaxf(m0, __shfl_xor_sync(0xffffffff, m0, 2));
    m1 = fmaxf(m1, __shfl_xor_sync(0xffffffff, m1, 1));
    m1 = fmaxf(m1, __shfl_xor_sync(0xffffffff, m1, 2));

    float l0 = 0.f, l1 = 0.f;
    #pragma unroll
    for (int nt = 0; nt < 16; nt++) {
        accS[nt][0] = __expf(accS[nt][0] - m0);
        accS[nt][1] = __expf(accS[nt][1] - m0);
        accS[nt][2] = __expf(accS[nt][2] - m1);
        accS[nt][3] = __expf(accS[nt][3] - m1);
        l0 += accS[nt][0] + accS[nt][1];
        l1 += accS[nt][2] + accS[nt][3];
    }
    l0 += __shfl_xor_sync(0xffffffff, l0, 1);
    l0 += __shfl_xor_sync(0xffffffff, l0, 2);
    l1 += __shfl_xor_sync(0xffffffff, l1, 1);
    l1 += __shfl_xor_sync(0xffffffff, l1, 2);
    float rl0 = 1.f / l0, rl1 = 1.f / l1;

    #pragma unroll
    for (int nt = 0; nt < 16; nt++) {
        __half2 p0 = __float22half2_rn(
            make_float2(accS[nt][0]*rl0, accS[nt][1]*rl0));
        __half2 p1 = __float22half2_rn(
            make_float2(accS[nt][2]*rl1, accS[nt][3]*rl1));
        Psw[(qrow+group  )*VS_W + nt*4 + tid4] = *reinterpret_cast<uint32_t*>(&p0);
        Psw[(qrow+group+8)*VS_W + nt*4 + tid4] = *reinterpret_cast<uint32_t*>(&p1);
    }
    __syncwarp();

    float accO[8][4];
    #pragma unroll
    for (int nt = 0; nt < 8; nt++)
        #pragma unroll
        for (int r = 0; r < 4; r++) accO[nt][r] = 0.f;

    const uint32_t pOff = ((qrow + lane15)*VS_W + lanehi*4)*4;
    uint32_t vOff[4];
    #pragma unroll
    for (int pr = 0; pr < 4; pr++) {
        int drow = pr*16 + (bsel>>1)*8 + (lane & 7);
        vOff[pr] = (drow*VS_W + (bsel & 1)*4)*4;
    }

    #pragma unroll
    for (int ks = 0; ks < 8; ks++) {
        const uint32_t kwB = ks * 32;
        uint32_t a0, a1, a2, a3;
        ldsm4(a0, a1, a2, a3, pBase + pOff + kwB);
        #pragma unroll
        for (int pr = 0; pr < 4; pr++) {
            uint32_t b00, b01, b10, b11;
            ldsm4(b00, b01, b10, b11, vBase + vOff[pr] + kwB);
            mma_f16(accO[pr*2  ], a0, a1, a2, a3, b00, b01);
            mma_f16(accO[pr*2+1], a0, a1, a2, a3, b10, b11);
        }
    }

    long row0 = (long)b*N_ + qb*128 + qrow + group;
    #pragma unroll
    for (int nt = 0; nt < 8; nt++) {
        int col = h*D_ + nt*8 + tid4*2;
        __half2 h0 = __float22half2_rn(make_float2(accO[nt][0], accO[nt][1]));
        __half2 h1 = __float22half2_rn(make_float2(accO[nt][2], accO[nt][3]));
        *reinterpret_cast<__half2*>(O + row0*C_ + col) = h0;
        *reinterpret_cast<__half2*>(O + (row0+8)*C_ + col) = h1;
    }
}

// ---------------------------------------------------------------------------
extern "C" void kernel_launch(void* const* d_in, const int* in_sizes, int n_in,
                              void* d_out, int out_size)
{
    const float* x      = (const float*)d_in[0];
    const float* Wqkv   = (const float*)d_in[1];
    const float* bqkv   = (const float*)d_in[2];
    const float* E_k    = (const float*)d_in[3];
    const float* E_v    = (const float*)d_in[4];
    const float* Wproj  = (const float*)d_in[5];
    const float* bproj  = (const float*)d_in[6];
    const float* k_bank = (const float*)d_in[7];
    const float* v_bank = (const float*)d_in[8];

    __half *xh, *Wqt, *Wpt, *Qh, *xph, *KVh, *kfh, *vth, *ao;
    cudaGetSymbolAddress((void**)&xh,  g_xh);
    cudaGetSymbolAddress((void**)&Wqt, g_Wqt);
    cudaGetSymbolAddress((void**)&Wpt, g_Wpt);
    cudaGetSymbolAddress((void**)&Qh,  g_Qh);
    cudaGetSymbolAddress((void**)&xph, g_xph);
    cudaGetSymbolAddress((void**)&KVh, g_KVh);
    cudaGetSymbolAddress((void**)&kfh, g_kfh);
    cudaGetSymbolAddress((void**)&vth, g_vth);
    cudaGetSymbolAddress((void**)&ao,  g_ao);

    cudaFuncSetAttribute(attn_tc,
                         cudaFuncAttributeMaxDynamicSharedMemorySize, ATTN_SMEM);

    // streams/events (host objects only; leaked by design)
    cudaStream_t s2;
    cudaStreamCreateWithFlags(&s2, cudaStreamNonBlocking);
    cudaEvent_t e0, eW, e1, eQ0, eQ1, eA0, eA1;
    cudaEventCreateWithFlags(&e0,  cudaEventDisableTiming);
    cudaEventCreateWithFlags(&eW,  cudaEventDisableTiming);
    cudaEventCreateWithFlags(&e1,  cudaEventDisableTiming);
    cudaEventCreateWithFlags(&eQ0, cudaEventDisableTiming);
    cudaEventCreateWithFlags(&eQ1, cudaEventDisableTiming);
    cudaEventCreateWithFlags(&eA0, cudaEventDisableTiming);
    cudaEventCreateWithFlags(&eA1, cudaEventDisableTiming);

    const long HALF_ROWS = (long)B_/2 * N_;            // 16384 rows
    const long HALF_Q    = HALF_ROWS * C_;             // element offset
    const int  HB        = B_/2;                       // 16 batches per half

    // fork s2
    cudaEventRecord(e0, 0);
    cudaStreamWaitEvent(s2, e0, 0);

    // s2: weight transposes
    f2h_T<<<dim3(3*C_/32, C_/32), dim3(32, 8), 0, s2>>>(Wqkv, Wqt, C_, 3*C_);
    f2h_T<<<dim3(C_/32, C_/32), dim3(32, 8), 0, s2>>>(Wproj, Wpt, C_, C_);
    cudaEventRecord(eW, s2);

    // main: fused x->fp16 + pooled tokens
    f2h_pool<<<(B_*N_*C_/4 + 255)/256, 256>>>(x, xh, xph);
    cudaEventRecord(e1, 0);

    // s2: KV projection + compress (needs xph; transposes already on s2)
    cudaStreamWaitEvent(s2, e1, 0);
    hgemm<<<dim3(2*C_/128, B_*L_/128), 256, 0, s2>>>(
        xph, Wqt + (long)C_*C_, bqkv + C_, KVh, C_, C_, C_, 2*C_, 1);
    kvcompress<<<dim3(2, H_, B_), 128, 0, s2>>>(
        KVh, E_k, E_v, k_bank, v_bank, kfh, vth);

    // main: Q projection halves (needs Wqt)
    cudaStreamWaitEvent(0, eW, 0);
    hgemm<<<dim3(C_/128, HALF_ROWS/128), 256>>>(
        xh, Wqt, bqkv, Qh, C_, C_, C_, C_, 1);
    cudaEventRecord(eQ0, 0);
    hgemm<<<dim3(C_/128, HALF_ROWS/128), 256>>>(
        xh + HALF_Q, Wqt, bqkv, Qh + HALF_Q, C_, C_, C_, C_, 1);
    cudaEventRecord(eQ1, 0);

    // s2: attention half 0 (batches 0..15) — overlaps Q half 1 on main
    cudaStreamWaitEvent(s2, eQ0, 0);
    attn_tc<<<dim3(N_/128, H_, HB), 256, ATTN_SMEM, s2>>>(
        Qh, kfh, vth, ao);
    cudaEventRecord(eA0, s2);

    // s2: attention half 1 — overlaps out-GEMM half 0 on main
    cudaStreamWaitEvent(s2, eQ1, 0);
    attn_tc<<<dim3(N_/128, H_, HB), 256, ATTN_SMEM, s2>>>(
        Qh + HALF_Q, kfh + (long)HB*H_*L_*D_, vth + (long)HB*H_*D_*L_,
        ao + HALF_Q);
    cudaEventRecord(eA1, s2);

    // main: out projection halves
    cudaStreamWaitEvent(0, eA0, 0);
    hgemm<<<dim3(C_/128, HALF_ROWS/128), 256>>>(
        ao, Wpt, bproj, (float*)d_out, C_, C_, C_, C_, 0);
    cudaStreamWaitEvent(0, eA1, 0);
    hgemm<<<dim3(C_/128, HALF_ROWS/128), 256>>>(
        ao + HALF_Q, Wpt, bproj, (float*)d_out + HALF_Q, C_, C_, C_, C_, 0);
}

// round 14
// speedup vs baseline: 1.0181x; 1.0181x over previous
#include <cuda_runtime.h>
#include <cuda_fp16.h>
#include <math.h>
#include <stdint.h>

#define B_  32
#define N_  1024
#define C_  768
#define H_  12
#define D_  64
#define L_  128

// ---------------- scratch (device globals: no allocations allowed) ----------
__device__ __half g_xh [B_*N_*C_];      // x in fp16
__device__ __half g_Wqt[3*C_*C_];       // Wqkv^T  [2304][768] fp16
__device__ __half g_Wpt[C_*C_];         // Wproj^T [768][768] fp16
__device__ __half g_Qh [B_*N_*C_];      // Q projection, fp16
__device__ __half g_xph[B_*L_*C_];      // pooled tokens, fp16
__device__ __half g_KVh[B_*L_*2*C_];    // K|V projections, fp16
__device__ __half g_kfh[B_*H_*L_*D_];   // k_full fp16 [bh][128][64]
__device__ __half g_vth[B_*H_*D_*L_];   // v_full fp16 TRANSPOSED [bh][64][128]
__device__ __half g_ao [B_*N_*C_];      // attention output, fp16

__device__ __forceinline__ void mma_f16(
    float* c, uint32_t a0, uint32_t a1, uint32_t a2, uint32_t a3,
    uint32_t b0, uint32_t b1)
{
    asm volatile(
        "mma.sync.aligned.m16n8k16.row.col.f32.f16.f16.f32 "
        "{%0,%1,%2,%3}, {%4,%5,%6,%7}, {%8,%9}, {%0,%1,%2,%3};"
        : "+f"(c[0]), "+f"(c[1]), "+f"(c[2]), "+f"(c[3])
        : "r"(a0), "r"(a1), "r"(a2), "r"(a3), "r"(b0), "r"(b1));
}

__device__ __forceinline__ void ldsm4(uint32_t& r0, uint32_t& r1,
                                      uint32_t& r2, uint32_t& r3, uint32_t addr)
{
    asm volatile("ldmatrix.sync.aligned.m8n8.x4.shared.b16 {%0,%1,%2,%3}, [%4];"
                 : "=r"(r0), "=r"(r1), "=r"(r2), "=r"(r3) : "r"(addr));
}

__device__ __forceinline__ void cp16(uint32_t saddr, const void* g) {
    asm volatile("cp.async.ca.shared.global [%0], [%1], 16;"
                 :: "r"(saddr), "l"(g));
}

// ------- fused fp32->fp16 convert of x, plus pooled-token generation --------
__global__ void f2h_pool(const float* __restrict__ x, __half* __restrict__ xh,
                         __half* __restrict__ xp)
{
    long i = (long)blockIdx.x * blockDim.x + threadIdx.x;   // float4 index
    const long TOT4 = (long)B_*N_*C_/4;
    if (i >= TOT4) return;
    int c4  = (int)(i % (C_/4));
    int row = (int)((i / (C_/4)) % N_);
    int b   = (int)(i / ((long)(C_/4) * N_));
    float4 v = *reinterpret_cast<const float4*>(x + i*4);
    __half2 h0 = __float22half2_rn(make_float2(v.x, v.y));
    __half2 h1 = __float22half2_rn(make_float2(v.z, v.w));
    uint2 o;
    o.x = *reinterpret_cast<uint32_t*>(&h0);
    o.y = *reinterpret_cast<uint32_t*>(&h1);
    *reinterpret_cast<uint2*>(xh + i*4) = o;

    if (row < 2*L_ && !(row & 1)) {
        float4 w = *reinterpret_cast<const float4*>(x + i*4 + C_);
        __half2 p0 = __float22half2_rn(
            make_float2(0.5f*(v.x+w.x), 0.5f*(v.y+w.y)));
        __half2 p1 = __float22half2_rn(
            make_float2(0.5f*(v.z+w.z), 0.5f*(v.w+w.w)));
        uint2 q;
        q.x = *reinterpret_cast<uint32_t*>(&p0);
        q.y = *reinterpret_cast<uint32_t*>(&p1);
        long pi = ((long)b*L_ + (row >> 1)) * C_ + c4*4;
        *reinterpret_cast<uint2*>(xp + pi) = q;
    }
}

// ---------------- fp32 -> fp16 transpose: Wt[c][r] = W[r][c] ----------------
__global__ void f2h_T(const float* __restrict__ W, __half* __restrict__ Wt,
                      int rows, int cols)
{
    __shared__ float s[32][33];
    int c0 = blockIdx.x*32, r0 = blockIdx.y*32;
    int tx = threadIdx.x, ty = threadIdx.y;   // 32 x 8
    #pragma unroll
    for (int i = 0; i < 32; i += 8)
        s[ty+i][tx] = W[(long)(r0+ty+i)*cols + c0+tx];
    __syncthreads();
    #pragma unroll
    for (int i = 0; i < 32; i += 8)
        Wt[(long)(c0+ty+i)*rows + r0+tx] = __float2half_rn(s[tx][ty+i]);
}

// -------- fp16 GEMM, cp.async double-buffered, ldmatrix fragments -----------
#define TH_STR 40      // halves per smem row (32 data + 8 pad); 20 words

__global__ __launch_bounds__(256, 2) void hgemm(
    const __half* __restrict__ A, const __half* __restrict__ Bt,
    const float* __restrict__ bias, void* __restrict__ Cv,
    int K, int lda, int ldbt, int ldc, int half_out)
{
    __shared__ __half Ah[2][128*TH_STR];
    __shared__ __half Bh[2][128*TH_STR];

    const int t    = threadIdx.x;
    const int warp = t >> 5;
    const int lane = t & 31;
    const int group = lane >> 2;
    const int tid4  = lane & 3;
    const int wm = (warp & 1) * 64;
    const int wn = (warp >> 1) * 32;

    const int bm = blockIdx.y * 128, bn = blockIdx.x * 128;

    float acc[4][4][4];
    #pragma unroll
    for (int mf = 0; mf < 4; mf++)
        #pragma unroll
        for (int nf = 0; nf < 4; nf++)
            #pragma unroll
            for (int r = 0; r < 4; r++) acc[mf][nf][r] = 0.f;

    const uint32_t aB0 = (uint32_t)__cvta_generic_to_shared(&Ah[0][0]);
    const uint32_t aB1 = (uint32_t)__cvta_generic_to_shared(&Ah[1][0]);
    const uint32_t bB0 = (uint32_t)__cvta_generic_to_shared(&Bh[0][0]);
    const uint32_t bB1 = (uint32_t)__cvta_generic_to_shared(&Bh[1][0]);

    const int lane15 = lane & 15;
    const int lanehi = lane >> 4;
    uint32_t aOff[4];
    #pragma unroll
    for (int mf = 0; mf < 4; mf++)
        aOff[mf] = ((wm + mf*16 + lane15)*20 + lanehi*4)*4;
    const int bsel = lane >> 3;
    uint32_t bOff[2];
    #pragma unroll
    for (int pr = 0; pr < 2; pr++) {
        int row = wn + (pr*2 + (bsel>>1))*8 + (lane & 7);
        bOff[pr] = (row*20 + (bsel & 1)*4)*4;
    }

    const int ar0 = t >> 2,        aof = (t & 3) * 8;
    const int ar1 = ar0 + 64;
    const int br  = t >> 1,        bof = (t & 1) * 16;

    const int ns = K >> 5;

    cp16(aB0 + (ar0*TH_STR + aof)*2, A + (long)(bm + ar0)*lda + aof);
    cp16(aB0 + (ar1*TH_STR + aof)*2, A + (long)(bm + ar1)*lda + aof);
    cp16(bB0 + (br*TH_STR + bof)*2,     Bt + (long)(bn + br)*ldbt + bof);
    cp16(bB0 + (br*TH_STR + bof + 8)*2, Bt + (long)(bn + br)*ldbt + bof + 8);
    asm volatile("cp.async.commit_group;");

    for (int i = 0; i < ns; i++) {
        const int buf = i & 1;
        asm volatile("cp.async.wait_all;" ::: "memory");
        __syncthreads();

        if (i + 1 < ns) {
            const int kn = (i + 1) << 5;
            const uint32_t aB = buf ? aB0 : aB1;
            const uint32_t bB = buf ? bB0 : bB1;
            cp16(aB + (ar0*TH_STR + aof)*2, A + (long)(bm + ar0)*lda + kn + aof);
            cp16(aB + (ar1*TH_STR + aof)*2, A + (long)(bm + ar1)*lda + kn + aof);
            cp16(bB + (br*TH_STR + bof)*2,     Bt + (long)(bn + br)*ldbt + kn + bof);
            cp16(bB + (br*TH_STR + bof + 8)*2, Bt + (long)(bn + br)*ldbt + kn + bof + 8);
            asm volatile("cp.async.commit_group;");
        }

        const uint32_t aB = buf ? aB1 : aB0;
        const uint32_t bB = buf ? bB1 : bB0;

        #pragma unroll
        for (int ks = 0; ks < 2; ks++) {
            const uint32_t kwB = ks * 8 * 4;
            uint32_t a[4][4], b[4][2];
            #pragma unroll
            for (int mf = 0; mf < 4; mf++)
                ldsm4(a[mf][0], a[mf][1], a[mf][2], a[mf][3],
                      aB + aOff[mf] + kwB);
            ldsm4(b[0][0], b[0][1], b[1][0], b[1][1], bB + bOff[0] + kwB);
            ldsm4(b[2][0], b[2][1], b[3][0], b[3][1], bB + bOff[1] + kwB);
            #pragma unroll
            for (int mf = 0; mf < 4; mf++)
                #pragma unroll
                for (int nf = 0; nf < 4; nf++)
                    mma_f16(acc[mf][nf], a[mf][0], a[mf][1], a[mf][2], a[mf][3],
                            b[nf][0], b[nf][1]);
        }
    }

    if (half_out) {
        __half* C = reinterpret_cast<__half*>(Cv);
        #pragma unroll
        for (int mf = 0; mf < 4; mf++) {
            long r0 = bm + wm + mf*16 + group;
            #pragma unroll
            for (int nf = 0; nf < 4; nf++) {
                int c0 = bn + wn + nf*8 + tid4*2;
                float2 bi = *reinterpret_cast<const float2*>(bias + c0);
                __half2 h0 = __float22half2_rn(
                    make_float2(acc[mf][nf][0] + bi.x, acc[mf][nf][1] + bi.y));
                __half2 h1 = __float22half2_rn(
                    make_float2(acc[mf][nf][2] + bi.x, acc[mf][nf][3] + bi.y));
                *reinterpret_cast<__half2*>(C + r0*ldc + c0) = h0;
                *reinterpret_cast<__half2*>(C + (r0+8)*ldc + c0) = h1;
            }
        }
    } else {
        float* C = reinterpret_cast<float*>(Cv);
        #pragma unroll
        for (int mf = 0; mf < 4; mf++) {
            long r0 = bm + wm + mf*16 + group;
            #pragma unroll
            for (int nf = 0; nf < 4; nf++) {
                int c0 = bn + wn + nf*8 + tid4*2;
                float2 bi = *reinterpret_cast<const float2*>(bias + c0);
                float2 o0, o1;
                o0.x = acc[mf][nf][0] + bi.x; o0.y = acc[mf][nf][1] + bi.y;
                o1.x = acc[mf][nf][2] + bi.x; o1.y = acc[mf][nf][3] + bi.y;
                *reinterpret_cast<float2*>(C + r0*ldc + c0) = o0;
                *reinterpret_cast<float2*>(C + (r0+8)*ldc + c0) = o1;
            }
        }
    }
}

// ------ tensor-core kvcompress: out = E^T @ KV_head (64x64x128), + bank -----
__global__ __launch_bounds__(128) void kvcompress(
    const __half* __restrict__ KV, const float* __restrict__ E_k,
    const float* __restrict__ E_v, const float* __restrict__ k_bank,
    const float* __restrict__ v_bank, __half* __restrict__ kf,
    __half* __restrict__ vt)
{
    __shared__ __half Et[64*136];
    __shared__ __half Kt[64*136];

    const int which = blockIdx.x, h = blockIdx.y, b = blockIdx.z;
    const float* E    = which ? E_v : E_k;
    const float* bank = which ? v_bank : k_bank;

    const int t = threadIdx.x;
    const int warp = t >> 5, lane = t & 31;
    const int group = lane >> 2, tid4 = lane & 3;

    for (int i = t*4; i < 128*64; i += 512) {
        int s = i >> 6, c = i & 63;
        float4 v = *reinterpret_cast<const float4*>(E + s*64 + c);
        Et[(c+0)*136 + s] = __float2half_rn(v.x);
        Et[(c+1)*136 + s] = __float2half_rn(v.y);
        Et[(c+2)*136 + s] = __float2half_rn(v.z);
        Et[(c+3)*136 + s] = __float2half_rn(v.w);
    }
    const __half* kvp = KV + (long)b*L_*2*C_ + which*C_ + h*D_;
    for (int i = t*4; i < 128*64; i += 512) {
        int s = i >> 6, d = i & 63;
        uint2 raw = *reinterpret_cast<const uint2*>(kvp + (long)s*2*C_ + d);
        const __half* hp = reinterpret_cast<const __half*>(&raw);
        Kt[(d+0)*136 + s] = hp[0];
        Kt[(d+1)*136 + s] = hp[1];
        Kt[(d+2)*136 + s] = hp[2];
        Kt[(d+3)*136 + s] = hp[3];
    }
    __syncthreads();

    float acc[8][4];
    #pragma unroll
    for (int nf = 0; nf < 8; nf++)
        #pragma unroll
        for (int r = 0; r < 4; r++) acc[nf][r] = 0.f;

    const uint32_t* Ew = reinterpret_cast<const uint32_t*>(Et);
    const uint32_t* Kw = reinterpret_cast<const uint32_t*>(Kt);
    const int m0 = warp*16 + group;

    #pragma unroll
    for (int ks = 0; ks < 8; ks++) {
        const int kw = ks * 8;
        uint32_t a0 = Ew[(m0    )*68 + kw + tid4];
        uint32_t a1 = Ew[(m0 + 8)*68 + kw + tid4];
        uint32_t a2 = Ew[(m0    )*68 + kw + tid4 + 4];
        uint32_t a3 = Ew[(m0 + 8)*68 + kw + tid4 + 4];
        #pragma unroll
        for (int nf = 0; nf < 8; nf++) {
            uint32_t b0 = Kw[(nf*8+group)*68 + kw + tid4];
            uint32_t b1 = Kw[(nf*8+group)*68 + kw + tid4 + 4];
            mma_f16(acc[nf], a0, a1, a2, a3, b0, b1);
        }
    }

    const long bh = (long)(b*H_ + h);
    if (which == 0) {
        __half* out = kf + bh*L_*D_;
        #pragma unroll
        for (int nf = 0; nf < 8; nf++) {
            int d = nf*8 + tid4*2;
            __half2 h0 = __float22half2_rn(make_float2(acc[nf][0], acc[nf][1]));
            __half2 h1 = __float22half2_rn(make_float2(acc[nf][2], acc[nf][3]));
            *reinterpret_cast<__half2*>(out + (m0  )*64 + d) = h0;
            *reinterpret_cast<__half2*>(out + (m0+8)*64 + d) = h1;
        }
        __syncthreads();
        for (int i = t*4; i < 64*64; i += 512) {
            int r = i >> 6, d = i & 63;
            float4 v = *reinterpret_cast<const float4*>(
                bank + (long)b*64*C_ + (long)r*C_ + h*D_ + d);
            __half2 h0 = __float22half2_rn(make_float2(v.x, v.y));
            __half2 h1 = __float22half2_rn(make_float2(v.z, v.w));
            *reinterpret_cast<__half2*>(out + (64+r)*64 + d) = h0;
            *reinterpret_cast<__half2*>(out + (64+r)*64 + d + 2) = h1;
        }
    } else {
        __half* out = vt + bh*D_*L_;
        #pragma unroll
        for (int nf = 0; nf < 8; nf++) {
            int d = nf*8 + tid4*2;
            out[(d  )*128 + m0    ] = __float2half_rn(acc[nf][0]);
            out[(d+1)*128 + m0    ] = __float2half_rn(acc[nf][1]);
            out[(d  )*128 + m0 + 8] = __float2half_rn(acc[nf][2]);
            out[(d+1)*128 + m0 + 8] = __float2half_rn(acc[nf][3]);
        }
        __syncthreads();
        for (int i = t*4; i < 64*64; i += 512) {
            int r = i >> 6, d = i & 63;
            float4 v = *reinterpret_cast<const float4*>(
                bank + (long)b*64*C_ + (long)r*C_ + h*D_ + d);
            out[(d  )*128 + 64 + r] = __float2half_rn(v.x);
            out[(d+1)*128 + 64 + r] = __float2half_rn(v.y);
            out[(d+2)*128 + 64 + r] = __float2half_rn(v.z);
            out[(d+3)*128 + 64 + r] = __float2half_rn(v.w);
        }
    }
}

// -------- fp16 tensor-core attention, ldmatrix fragments --------------------
#define QS_W 36
#define VS_W 68
#define ATTN_SMEM ((128*QS_W + 64*VS_W + 128*VS_W + 128*QS_W) * 4)

__global__ __launch_bounds__(256, 2) void attn_tc(
    const __half* __restrict__ Q, const __half* __restrict__ kf,
    const __half* __restrict__ vt, __half* __restrict__ O)
{
    extern __shared__ uint32_t smu[];
    uint32_t* Ksw = smu;                      // [128][36]
    uint32_t* Vtw = Ksw + 128*QS_W;           // [64][68]
    uint32_t* Psw = Vtw + 64*VS_W;            // [128][68]
    uint32_t* Qsw = Psw + 128*VS_W;           // [128][36]

    const int t = threadIdx.x;
    const int warp = t >> 5, lane = t & 31;
    const int group = lane >> 2, tid4 = lane & 3;
    const int qb = blockIdx.x, h = blockIdx.y, b = blockIdx.z;

    const __half* kfp = kf + (long)(b*H_ + h) * L_ * D_;
    const __half* vtp = vt + (long)(b*H_ + h) * D_ * L_;

    for (int i = t*8; i < L_*D_; i += 2048) {
        int k = i >> 6, d = i & 63;
        *reinterpret_cast<uint4*>(&Ksw[k*QS_W + (d>>1)]) =
            *reinterpret_cast<const uint4*>(kfp + i);
    }
    for (int i = t*8; i < D_*L_; i += 2048) {
        int d = i >> 7, k = i & 127;
        *reinterpret_cast<uint4*>(&Vtw[d*VS_W + (k>>1)]) =
            *reinterpret_cast<const uint4*>(vtp + i);
    }
    {
        long base = ((long)b*N_ + qb*128) * C_ + h*D_;
        for (int i = t*8; i < 128*64; i += 2048) {
            int q = i >> 6, d = i & 63;
            *reinterpret_cast<uint4*>(&Qsw[q*QS_W + (d>>1)]) =
                *reinterpret_cast<const uint4*>(Q + base + (long)q*C_ + d);
        }
    }
    __syncthreads();

    const uint32_t kBase = (uint32_t)__cvta_generic_to_shared(Ksw);
    const uint32_t vBase = (uint32_t)__cvta_generic_to_shared(Vtw);
    const uint32_t pBase = (uint32_t)__cvta_generic_to_shared(Psw);
    const uint32_t qBase = (uint32_t)__cvta_generic_to_shared(Qsw);

    const int lane15 = lane & 15;
    const int lanehi = lane >> 4;
    const int bsel = lane >> 3;
    const int qrow = warp*16;

    float accS[16][4];
    #pragma unroll
    for (int nt = 0; nt < 16; nt++)
        #pragma unroll
        for (int r = 0; r < 4; r++) accS[nt][r] = 0.f;

    const uint32_t qOff = ((qrow + lane15)*QS_W + lanehi*4)*4;
    uint32_t kOff[8];
    #pragma unroll
    for (int pr = 0; pr < 8; pr++) {
        int krow = pr*16 + (bsel>>1)*8 + (lane & 7);
        kOff[pr] = (krow*QS_W + (bsel & 1)*4)*4;
    }

    #pragma unroll
    for (int ks = 0; ks < 4; ks++) {
        const uint32_t kwB = ks * 32;
        uint32_t a0, a1, a2, a3;
        ldsm4(a0, a1, a2, a3, qBase + qOff + kwB);
        #pragma unroll
        for (int pr = 0; pr < 8; pr++) {
            uint32_t b00, b01, b10, b11;
            ldsm4(b00, b01, b10, b11, kBase + kOff[pr] + kwB);
            mma_f16(accS[pr*2  ], a0, a1, a2, a3, b00, b01);
            mma_f16(accS[pr*2+1], a0, a1, a2, a3, b10, b11);
        }
    }

    const float scale = 0.125f;
    float m0 = -1e30f, m1 = -1e30f;
    #pragma unroll
    for (int nt = 0; nt < 16; nt++) {
        accS[nt][0] *= scale; accS[nt][1] *= scale;
        accS[nt][2] *= scale; accS[nt][3] *= scale;
        m0 = fmaxf(m0, fmaxf(accS[nt][0], accS[nt][1]));
        m1 = fmaxf(m1, fmaxf(accS[nt][2], accS[nt][3]));
    }
    m0 = fmaxf(m0, __shfl_xor_sync(0xffffffff, m0, 1));
    m0 = fmaxf(m0, __shfl_xor_sync(0xffffffff, m0, 2));
    m1 = fmaxf(m1, __shfl_xor_sync(0xffffffff, m1, 1));
    m1 = fmaxf(m1, __shfl_xor_sync(0xffffffff, m1, 2));

    float l0 = 0.f, l1 = 0.f;
    #pragma unroll
    for (int nt = 0; nt < 16; nt++) {
        accS[nt][0] = __expf(accS[nt][0] - m0);
        accS[nt][1] = __expf(accS[nt][1] - m0);
        accS[nt][2] = __expf(accS[nt][2] - m1);
        accS[nt][3] = __expf(accS[nt][3] - m1);
        l0 += accS[nt][0] + accS[nt][1];
        l1 += accS[nt][2] + accS[nt][3];
    }
    l0 += __shfl_xor_sync(0xffffffff, l0, 1);
    l0 += __shfl_xor_sync(0xffffffff, l0, 2);
    l1 += __shfl_xor_sync(0xffffffff, l1, 1);
    l1 += __shfl_xor_sync(0xffffffff, l1, 2);
    float rl0 = 1.f / l0, rl1 = 1.f / l1;

    #pragma unroll
    for (int nt = 0; nt < 16; nt++) {
        __half2 p0 = __float22half2_rn(
            make_float2(accS[nt][0]*rl0, accS[nt][1]*rl0));
        __half2 p1 = __float22half2_rn(
            make_float2(accS[nt][2]*rl1, accS[nt][3]*rl1));
        Psw[(qrow+group  )*VS_W + nt*4 + tid4] = *reinterpret_cast<uint32_t*>(&p0);
        Psw[(qrow+group+8)*VS_W + nt*4 + tid4] = *reinterpret_cast<uint32_t*>(&p1);
    }
    __syncwarp();

    float accO[8][4];
    #pragma unroll
    for (int nt = 0; nt < 8; nt++)
        #pragma unroll
        for (int r = 0; r < 4; r++) accO[nt][r] = 0.f;

    const uint32_t pOff = ((qrow + lane15)*VS_W + lanehi*4)*4;
    uint32_t vOff[4];
    #pragma unroll
    for (int pr = 0; pr < 4; pr++) {
        int drow = pr*16 + (bsel>>1)*8 + (lane & 7);
        vOff[pr] = (drow*VS_W + (bsel & 1)*4)*4;
    }

    #pragma unroll
    for (int ks = 0; ks < 8; ks++) {
        const uint32_t kwB = ks * 32;
        uint32_t a0, a1, a2, a3;
        ldsm4(a0, a1, a2, a3, pBase + pOff + kwB);
        #pragma unroll
        for (int pr = 0; pr < 4; pr++) {
            uint32_t b00, b01, b10, b11;
            ldsm4(b00, b01, b10, b11, vBase + vOff[pr] + kwB);
            mma_f16(accO[pr*2  ], a0, a1, a2, a3, b00, b01);
            mma_f16(accO[pr*2+1], a0, a1, a2, a3, b10, b11);
        }
    }

    long row0 = (long)b*N_ + qb*128 + qrow + group;
    #pragma unroll
    for (int nt = 0; nt < 8; nt++) {
        int col = h*D_ + nt*8 + tid4*2;
        __half2 h0 = __float22half2_rn(make_float2(accO[nt][0], accO[nt][1]));
        __half2 h1 = __float22half2_rn(make_float2(accO[nt][2], accO[nt][3]));
        *reinterpret_cast<__half2*>(O + row0*C_ + col) = h0;
        *reinterpret_cast<__half2*>(O + (row0+8)*C_ + col) = h1;
    }
}

// ---------------------------------------------------------------------------
extern "C" void kernel_launch(void* const* d_in, const int* in_sizes, int n_in,
                              void* d_out, int out_size)
{
    const float* x      = (const float*)d_in[0];
    const float* Wqkv   = (const float*)d_in[1];
    const float* bqkv   = (const float*)d_in[2];
    const float* E_k    = (const float*)d_in[3];
    const float* E_v    = (const float*)d_in[4];
    const float* Wproj  = (const float*)d_in[5];
    const float* bproj  = (const float*)d_in[6];
    const float* k_bank = (const float*)d_in[7];
    const float* v_bank = (const float*)d_in[8];

    __half *xh, *Wqt, *Wpt, *Qh, *xph, *KVh, *kfh, *vth, *ao;
    cudaGetSymbolAddress((void**)&xh,  g_xh);
    cudaGetSymbolAddress((void**)&Wqt, g_Wqt);
    cudaGetSymbolAddress((void**)&Wpt, g_Wpt);
    cudaGetSymbolAddress((void**)&Qh,  g_Qh);
    cudaGetSymbolAddress((void**)&xph, g_xph);
    cudaGetSymbolAddress((void**)&KVh, g_KVh);
    cudaGetSymbolAddress((void**)&kfh, g_kfh);
    cudaGetSymbolAddress((void**)&vth, g_vth);
    cudaGetSymbolAddress((void**)&ao,  g_ao);

    cudaFuncSetAttribute(attn_tc,
                         cudaFuncAttributeMaxDynamicSharedMemorySize, ATTN_SMEM);

    // streams/events (host objects only; leaked by design)
    cudaStream_t s2;
    cudaStreamCreateWithFlags(&s2, cudaStreamNonBlocking);
    cudaEvent_t e0, eW, e1, e2, eA0, eO0;
    cudaEventCreateWithFlags(&e0,  cudaEventDisableTiming);
    cudaEventCreateWithFlags(&eW,  cudaEventDisableTiming);
    cudaEventCreateWithFlags(&e1,  cudaEventDisableTiming);
    cudaEventCreateWithFlags(&e2,  cudaEventDisableTiming);
    cudaEventCreateWithFlags(&eA0, cudaEventDisableTiming);
    cudaEventCreateWithFlags(&eO0, cudaEventDisableTiming);

    const long HALF_ROWS = (long)B_/2 * N_;            // 16384 rows
    const long HALF_Q    = HALF_ROWS * C_;             // element offset
    const int  HB        = B_/2;                       // 16 batches per half

    // fork s2
    cudaEventRecord(e0, 0);
    cudaStreamWaitEvent(s2, e0, 0);

    // s2: weight transposes
    f2h_T<<<dim3(3*C_/32, C_/32), dim3(32, 8), 0, s2>>>(Wqkv, Wqt, C_, 3*C_);
    f2h_T<<<dim3(C_/32, C_/32), dim3(32, 8), 0, s2>>>(Wproj, Wpt, C_, C_);
    cudaEventRecord(eW, s2);

    // main: fused x->fp16 + pooled tokens
    f2h_pool<<<(B_*N_*C_/4 + 255)/256, 256>>>(x, xh, xph);
    cudaEventRecord(e1, 0);

    // s2: KV projection + compress (needs xph)
    cudaStreamWaitEvent(s2, e1, 0);
    hgemm<<<dim3(2*C_/128, B_*L_/128), 256, 0, s2>>>(
        xph, Wqt + (long)C_*C_, bqkv + C_, KVh, C_, C_, C_, 2*C_, 1);
    kvcompress<<<dim3(2, H_, B_), 128, 0, s2>>>(
        KVh, E_k, E_v, k_bank, v_bank, kfh, vth);
    cudaEventRecord(e2, s2);

    // main: FULL Q projection (needs Wqt)
    cudaStreamWaitEvent(0, eW, 0);
    hgemm<<<dim3(C_/128, B_*N_/128), 256>>>(xh, Wqt, bqkv, Qh,
                                            C_, C_, C_, C_, 1);

    // main: attention half 0 (batches 0..15), then half 1
    cudaStreamWaitEvent(0, e2, 0);
    attn_tc<<<dim3(N_/128, H_, HB), 256, ATTN_SMEM>>>(Qh, kfh, vth, ao);
    cudaEventRecord(eA0, 0);
    attn_tc<<<dim3(N_/128, H_, HB), 256, ATTN_SMEM>>>(
        Qh + HALF_Q, kfh + (long)HB*H_*L_*D_, vth + (long)HB*H_*D_*L_,
        ao + HALF_Q);

    // s2: out-GEMM half 0 (rows of batches 0..15) — overlaps attn half 1
    cudaStreamWaitEvent(s2, eA0, 0);
    hgemm<<<dim3(C_/128, HALF_ROWS/128), 256, 0, s2>>>(
        ao, Wpt, bproj, (float*)d_out, C_, C_, C_, C_, 0);
    cudaEventRecord(eO0, s2);

    // main: out-GEMM half 1, then join s2
    hgemm<<<dim3(C_/128, HALF_ROWS/128), 256>>>(
        ao + HALF_Q, Wpt, bproj, (float*)d_out + HALF_Q, C_, C_, C_, C_, 0);
    cudaStreamWaitEvent(0, eO0, 0);
}

// round 15
// speedup vs baseline: 1.0374x; 1.0190x over previous
#include <cuda_runtime.h>
#include <cuda_fp16.h>
#include <math.h>
#include <stdint.h>

#define B_  32
#define N_  1024
#define C_  768
#define H_  12
#define D_  64
#define L_  128

// ---------------- scratch (device globals: no allocations allowed) ----------
__device__ __half g_xh [B_*N_*C_];      // x in fp16
__device__ __half g_Wqt[3*C_*C_];       // Wqkv^T  [2304][768] fp16
__device__ __half g_Wpt[C_*C_];         // Wproj^T [768][768] fp16
__device__ __half g_Qh [B_*N_*C_];      // Q projection, fp16
__device__ __half g_xph[B_*L_*C_];      // pooled tokens, fp16
__device__ __half g_KVh[B_*L_*2*C_];    // K|V projections, fp16
__device__ __half g_kfh[B_*H_*L_*D_];   // k_full fp16 [bh][128][64]
__device__ __half g_vth[B_*H_*D_*L_];   // v_full fp16 TRANSPOSED [bh][64][128]
__device__ __half g_ao [B_*N_*C_];      // attention output, fp16

__device__ __forceinline__ void mma_f16(
    float* c, uint32_t a0, uint32_t a1, uint32_t a2, uint32_t a3,
    uint32_t b0, uint32_t b1)
{
    asm volatile(
        "mma.sync.aligned.m16n8k16.row.col.f32.f16.f16.f32 "
        "{%0,%1,%2,%3}, {%4,%5,%6,%7}, {%8,%9}, {%0,%1,%2,%3};"
        : "+f"(c[0]), "+f"(c[1]), "+f"(c[2]), "+f"(c[3])
        : "r"(a0), "r"(a1), "r"(a2), "r"(a3), "r"(b0), "r"(b1));
}

__device__ __forceinline__ void ldsm4(uint32_t& r0, uint32_t& r1,
                                      uint32_t& r2, uint32_t& r3, uint32_t addr)
{
    asm volatile("ldmatrix.sync.aligned.m8n8.x4.shared.b16 {%0,%1,%2,%3}, [%4];"
                 : "=r"(r0), "=r"(r1), "=r"(r2), "=r"(r3) : "r"(addr));
}

__device__ __forceinline__ void cp16(uint32_t saddr, const void* g) {
    asm volatile("cp.async.ca.shared.global [%0], [%1], 16;"
                 :: "r"(saddr), "l"(g));
}

// ---------------- pure fp32 -> fp16 convert, MLP=4 --------------------------
// grid = TOT4/(256*4); each thread converts 4 float4s at stride grid*256.
__global__ void f2h4(const float* __restrict__ s, __half* __restrict__ d)
{
    const long stride = (long)gridDim.x * 256;
    long i0 = (long)blockIdx.x * 256 + threadIdx.x;
    float4 v0 = *reinterpret_cast<const float4*>(s + (i0           )*4);
    float4 v1 = *reinterpret_cast<const float4*>(s + (i0 +   stride)*4);
    float4 v2 = *reinterpret_cast<const float4*>(s + (i0 + 2*stride)*4);
    float4 v3 = *reinterpret_cast<const float4*>(s + (i0 + 3*stride)*4);
    #pragma unroll
    for (int k = 0; k < 4; k++) {
        float4 v = (k==0) ? v0 : (k==1) ? v1 : (k==2) ? v2 : v3;
        __half2 h0 = __float22half2_rn(make_float2(v.x, v.y));
        __half2 h1 = __float22half2_rn(make_float2(v.z, v.w));
        uint2 o;
        o.x = *reinterpret_cast<uint32_t*>(&h0);
        o.y = *reinterpret_cast<uint32_t*>(&h1);
        *reinterpret_cast<uint2*>(d + (i0 + k*stride)*4) = o;
    }
}

// ---------------- pooling -> fp16: xp[b,p,c] = .5*(x[2p]+x[2p+1]) -----------
__global__ void pool_kernel(const float* __restrict__ x, __half* __restrict__ xp)
{
    int i = blockIdx.x * blockDim.x + threadIdx.x;      // 4-elem index
    const int TOT4 = B_*L_*C_/4;
    if (i >= TOT4) return;
    int c4 = i % (C_/4);
    int p  = (i / (C_/4)) % L_;
    int b  = i / (C_/4 * L_);
    long base = (long)b*N_*C_ + (long)(2*p)*C_ + c4*4;
    float4 a = *reinterpret_cast<const float4*>(x + base);
    float4 c = *reinterpret_cast<const float4*>(x + base + C_);
    __half2 h0 = __float22half2_rn(make_float2(0.5f*(a.x+c.x), 0.5f*(a.y+c.y)));
    __half2 h1 = __float22half2_rn(make_float2(0.5f*(a.z+c.z), 0.5f*(a.w+c.w)));
    uint2 o;
    o.x = *reinterpret_cast<uint32_t*>(&h0);
    o.y = *reinterpret_cast<uint32_t*>(&h1);
    *reinterpret_cast<uint2*>(xp + (long)i*4) = o;
}

// ---------------- fp32 -> fp16 transpose: Wt[c][r] = W[r][c] ----------------
__global__ void f2h_T(const float* __restrict__ W, __half* __restrict__ Wt,
                      int rows, int cols)
{
    __shared__ float s[32][33];
    int c0 = blockIdx.x*32, r0 = blockIdx.y*32;
    int tx = threadIdx.x, ty = threadIdx.y;   // 32 x 8
    #pragma unroll
    for (int i = 0; i < 32; i += 8)
        s[ty+i][tx] = W[(long)(r0+ty+i)*cols + c0+tx];
    __syncthreads();
    #pragma unroll
    for (int i = 0; i < 32; i += 8)
        Wt[(long)(c0+ty+i)*rows + r0+tx] = __float2half_rn(s[tx][ty+i]);
}

// -------- fp16 GEMM, cp.async double-buffered, ldmatrix fragments -----------
#define TH_STR 40      // halves per smem row (32 data + 8 pad); 20 words

__global__ __launch_bounds__(256, 2) void hgemm(
    const __half* __restrict__ A, const __half* __restrict__ Bt,
    const float* __restrict__ bias, void* __restrict__ Cv,
    int K, int lda, int ldbt, int ldc, int half_out)
{
    __shared__ __half Ah[2][128*TH_STR];
    __shared__ __half Bh[2][128*TH_STR];

    const int t    = threadIdx.x;
    const int warp = t >> 5;
    const int lane = t & 31;
    const int group = lane >> 2;
    const int tid4  = lane & 3;
    const int wm = (warp & 1) * 64;
    const int wn = (warp >> 1) * 32;

    const int bm = blockIdx.y * 128, bn = blockIdx.x * 128;

    float acc[4][4][4];
    #pragma unroll
    for (int mf = 0; mf < 4; mf++)
        #pragma unroll
        for (int nf = 0; nf < 4; nf++)
            #pragma unroll
            for (int r = 0; r < 4; r++) acc[mf][nf][r] = 0.f;

    const uint32_t aB0 = (uint32_t)__cvta_generic_to_shared(&Ah[0][0]);
    const uint32_t aB1 = (uint32_t)__cvta_generic_to_shared(&Ah[1][0]);
    const uint32_t bB0 = (uint32_t)__cvta_generic_to_shared(&Bh[0][0]);
    const uint32_t bB1 = (uint32_t)__cvta_generic_to_shared(&Bh[1][0]);

    const int lane15 = lane & 15;
    const int lanehi = lane >> 4;
    uint32_t aOff[4];
    #pragma unroll
    for (int mf = 0; mf < 4; mf++)
        aOff[mf] = ((wm + mf*16 + lane15)*20 + lanehi*4)*4;
    const int bsel = lane >> 3;
    uint32_t bOff[2];
    #pragma unroll
    for (int pr = 0; pr < 2; pr++) {
        int row = wn + (pr*2 + (bsel>>1))*8 + (lane & 7);
        bOff[pr] = (row*20 + (bsel & 1)*4)*4;
    }

    const int ar0 = t >> 2,        aof = (t & 3) * 8;
    const int ar1 = ar0 + 64;
    const int br  = t >> 1,        bof = (t & 1) * 16;

    const int ns = K >> 5;

    cp16(aB0 + (ar0*TH_STR + aof)*2, A + (long)(bm + ar0)*lda + aof);
    cp16(aB0 + (ar1*TH_STR + aof)*2, A + (long)(bm + ar1)*lda + aof);
    cp16(bB0 + (br*TH_STR + bof)*2,     Bt + (long)(bn + br)*ldbt + bof);
    cp16(bB0 + (br*TH_STR + bof + 8)*2, Bt + (long)(bn + br)*ldbt + bof + 8);
    asm volatile("cp.async.commit_group;");

    for (int i = 0; i < ns; i++) {
        const int buf = i & 1;
        asm volatile("cp.async.wait_all;" ::: "memory");
        __syncthreads();

        if (i + 1 < ns) {
            const int kn = (i + 1) << 5;
            const uint32_t aB = buf ? aB0 : aB1;
            const uint32_t bB = buf ? bB0 : bB1;
            cp16(aB + (ar0*TH_STR + aof)*2, A + (long)(bm + ar0)*lda + kn + aof);
            cp16(aB + (ar1*TH_STR + aof)*2, A + (long)(bm + ar1)*lda + kn + aof);
            cp16(bB + (br*TH_STR + bof)*2,     Bt + (long)(bn + br)*ldbt + kn + bof);
            cp16(bB + (br*TH_STR + bof + 8)*2, Bt + (long)(bn + br)*ldbt + kn + bof + 8);
            asm volatile("cp.async.commit_group;");
        }

        const uint32_t aB = buf ? aB1 : aB0;
        const uint32_t bB = buf ? bB1 : bB0;

        #pragma unroll
        for (int ks = 0; ks < 2; ks++) {
            const uint32_t kwB = ks * 8 * 4;
            uint32_t a[4][4], b[4][2];
            #pragma unroll
            for (int mf = 0; mf < 4; mf++)
                ldsm4(a[mf][0], a[mf][1], a[mf][2], a[mf][3],
                      aB + aOff[mf] + kwB);
            ldsm4(b[0][0], b[0][1], b[1][0], b[1][1], bB + bOff[0] + kwB);
            ldsm4(b[2][0], b[2][1], b[3][0], b[3][1], bB + bOff[1] + kwB);
            #pragma unroll
            for (int mf = 0; mf < 4; mf++)
                #pragma unroll
                for (int nf = 0; nf < 4; nf++)
                    mma_f16(acc[mf][nf], a[mf][0], a[mf][1], a[mf][2], a[mf][3],
                            b[nf][0], b[nf][1]);
        }
    }

    if (half_out) {
        __half* C = reinterpret_cast<__half*>(Cv);
        #pragma unroll
        for (int mf = 0; mf < 4; mf++) {
            long r0 = bm + wm + mf*16 + group;
            #pragma unroll
            for (int nf = 0; nf < 4; nf++) {
                int c0 = bn + wn + nf*8 + tid4*2;
                float2 bi = *reinterpret_cast<const float2*>(bias + c0);
                __half2 h0 = __float22half2_rn(
                    make_float2(acc[mf][nf][0] + bi.x, acc[mf][nf][1] + bi.y));
                __half2 h1 = __float22half2_rn(
                    make_float2(acc[mf][nf][2] + bi.x, acc[mf][nf][3] + bi.y));
                *reinterpret_cast<__half2*>(C + r0*ldc + c0) = h0;
                *reinterpret_cast<__half2*>(C + (r0+8)*ldc + c0) = h1;
            }
        }
    } else {
        float* C = reinterpret_cast<float*>(Cv);
        #pragma unroll
        for (int mf = 0; mf < 4; mf++) {
            long r0 = bm + wm + mf*16 + group;
            #pragma unroll
            for (int nf = 0; nf < 4; nf++) {
                int c0 = bn + wn + nf*8 + tid4*2;
                float2 bi = *reinterpret_cast<const float2*>(bias + c0);
                float2 o0, o1;
                o0.x = acc[mf][nf][0] + bi.x; o0.y = acc[mf][nf][1] + bi.y;
                o1.x = acc[mf][nf][2] + bi.x; o1.y = acc[mf][nf][3] + bi.y;
                *reinterpret_cast<float2*>(C + r0*ldc + c0) = o0;
                *reinterpret_cast<float2*>(C + (r0+8)*ldc + c0) = o1;
            }
        }
    }
}

// ------ tensor-core kvcompress: out = E^T @ KV_head (64x64x128), + bank -----
__global__ __launch_bounds__(128) void kvcompress(
    const __half* __restrict__ KV, const float* __restrict__ E_k,
    const float* __restrict__ E_v, const float* __restrict__ k_bank,
    const float* __restrict__ v_bank, __half* __restrict__ kf,
    __half* __restrict__ vt)
{
    __shared__ __half Et[64*136];
    __shared__ __half Kt[64*136];

    const int which = blockIdx.x, h = blockIdx.y, b = blockIdx.z;
    const float* E    = which ? E_v : E_k;
    const float* bank = which ? v_bank : k_bank;

    const int t = threadIdx.x;
    const int warp = t >> 5, lane = t & 31;
    const int group = lane >> 2, tid4 = lane & 3;

    for (int i = t*4; i < 128*64; i += 512) {
        int s = i >> 6, c = i & 63;
        float4 v = *reinterpret_cast<const float4*>(E + s*64 + c);
        Et[(c+0)*136 + s] = __float2half_rn(v.x);
        Et[(c+1)*136 + s] = __float2half_rn(v.y);
        Et[(c+2)*136 + s] = __float2half_rn(v.z);
        Et[(c+3)*136 + s] = __float2half_rn(v.w);
    }
    const __half* kvp = KV + (long)b*L_*2*C_ + which*C_ + h*D_;
    for (int i = t*4; i < 128*64; i += 512) {
        int s = i >> 6, d = i & 63;
        uint2 raw = *reinterpret_cast<const uint2*>(kvp + (long)s*2*C_ + d);
        const __half* hp = reinterpret_cast<const __half*>(&raw);
        Kt[(d+0)*136 + s] = hp[0];
        Kt[(d+1)*136 + s] = hp[1];
        Kt[(d+2)*136 + s] = hp[2];
        Kt[(d+3)*136 + s] = hp[3];
    }
    __syncthreads();

    float acc[8][4];
    #pragma unroll
    for (int nf = 0; nf < 8; nf++)
        #pragma unroll
        for (int r = 0; r < 4; r++) acc[nf][r] = 0.f;

    const uint32_t* Ew = reinterpret_cast<const uint32_t*>(Et);
    const uint32_t* Kw = reinterpret_cast<const uint32_t*>(Kt);
    const int m0 = warp*16 + group;

    #pragma unroll
    for (int ks = 0; ks < 8; ks++) {
        const int kw = ks * 8;
        uint32_t a0 = Ew[(m0    )*68 + kw + tid4];
        uint32_t a1 = Ew[(m0 + 8)*68 + kw + tid4];
        uint32_t a2 = Ew[(m0    )*68 + kw + tid4 + 4];
        uint32_t a3 = Ew[(m0 + 8)*68 + kw + tid4 + 4];
        #pragma unroll
        for (int nf = 0; nf < 8; nf++) {
            uint32_t b0 = Kw[(nf*8+group)*68 + kw + tid4];
            uint32_t b1 = Kw[(nf*8+group)*68 + kw + tid4 + 4];
            mma_f16(acc[nf], a0, a1, a2, a3, b0, b1);
        }
    }

    const long bh = (long)(b*H_ + h);
    if (which == 0) {
        __half* out = kf + bh*L_*D_;
        #pragma unroll
        for (int nf = 0; nf < 8; nf++) {
            int d = nf*8 + tid4*2;
            __half2 h0 = __float22half2_rn(make_float2(acc[nf][0], acc[nf][1]));
            __half2 h1 = __float22half2_rn(make_float2(acc[nf][2], acc[nf][3]));
            *reinterpret_cast<__half2*>(out + (m0  )*64 + d) = h0;
            *reinterpret_cast<__half2*>(out + (m0+8)*64 + d) = h1;
        }
        __syncthreads();
        for (int i = t*4; i < 64*64; i += 512) {
            int r = i >> 6, d = i & 63;
            float4 v = *reinterpret_cast<const float4*>(
                bank + (long)b*64*C_ + (long)r*C_ + h*D_ + d);
            __half2 h0 = __float22half2_rn(make_float2(v.x, v.y));
            __half2 h1 = __float22half2_rn(make_float2(v.z, v.w));
            *reinterpret_cast<__half2*>(out + (64+r)*64 + d) = h0;
            *reinterpret_cast<__half2*>(out + (64+r)*64 + d + 2) = h1;
        }
    } else {
        __half* out = vt + bh*D_*L_;
        #pragma unroll
        for (int nf = 0; nf < 8; nf++) {
            int d = nf*8 + tid4*2;
            out[(d  )*128 + m0    ] = __float2half_rn(acc[nf][0]);
            out[(d+1)*128 + m0    ] = __float2half_rn(acc[nf][1]);
            out[(d  )*128 + m0 + 8] = __float2half_rn(acc[nf][2]);
            out[(d+1)*128 + m0 + 8] = __float2half_rn(acc[nf][3]);
        }
        __syncthreads();
        for (int i = t*4; i < 64*64; i += 512) {
            int r = i >> 6, d = i & 63;
            float4 v = *reinterpret_cast<const float4*>(
                bank + (long)b*64*C_ + (long)r*C_ + h*D_ + d);
            out[(d  )*128 + 64 + r] = __float2half_rn(v.x);
            out[(d+1)*128 + 64 + r] = __float2half_rn(v.y);
            out[(d+2)*128 + 64 + r] = __float2half_rn(v.z);
            out[(d+3)*128 + 64 + r] = __float2half_rn(v.w);
        }
    }
}

// -------- fp16 tensor-core attention, ldmatrix fragments --------------------
#define QS_W 36
#define VS_W 68
#define ATTN_SMEM ((128*QS_W + 64*VS_W + 128*VS_W + 128*QS_W) * 4)

__global__ __launch_bounds__(256, 2) void attn_tc(
    const __half* __restrict__ Q, const __half* __restrict__ kf,
    const __half* __restrict__ vt, __half* __restrict__ O)
{
    extern __shared__ uint32_t smu[];
    uint32_t* Ksw = smu;                      // [128][36]
    uint32_t* Vtw = Ksw + 128*QS_W;           // [64][68]
    uint32_t* Psw = Vtw + 64*VS_W;            // [128][68]
    uint32_t* Qsw = Psw + 128*VS_W;           // [128][36]

    const int t = threadIdx.x;
    const int warp = t >> 5, lane = t & 31;
    const int group = lane >> 2, tid4 = lane & 3;
    const int qb = blockIdx.x, h = blockIdx.y, b = blockIdx.z;

    const __half* kfp = kf + (long)(b*H_ + h) * L_ * D_;
    const __half* vtp = vt + (long)(b*H_ + h) * D_ * L_;

    for (int i = t*8; i < L_*D_; i += 2048) {
        int k = i >> 6, d = i & 63;
        *reinterpret_cast<uint4*>(&Ksw[k*QS_W + (d>>1)]) =
            *reinterpret_cast<const uint4*>(kfp + i);
    }
    for (int i = t*8; i < D_*L_; i += 2048) {
        int d = i >> 7, k = i & 127;
        *reinterpret_cast<uint4*>(&Vtw[d*VS_W + (k>>1)]) =
            *reinterpret_cast<const uint4*>(vtp + i);
    }
    {
        long base = ((long)b*N_ + qb*128) * C_ + h*D_;
        for (int i = t*8; i < 128*64; i += 2048) {
            int q = i >> 6, d = i & 63;
            *reinterpret_cast<uint4*>(&Qsw[q*QS_W + (d>>1)]) =
                *reinterpret_cast<const uint4*>(Q + base + (long)q*C_ + d);
        }
    }
    __syncthreads();

    const uint32_t kBase = (uint32_t)__cvta_generic_to_shared(Ksw);
    const uint32_t vBase = (uint32_t)__cvta_generic_to_shared(Vtw);
    const uint32_t pBase = (uint32_t)__cvta_generic_to_shared(Psw);
    const uint32_t qBase = (uint32_t)__cvta_generic_to_shared(Qsw);

    const int lane15 = lane & 15;
    const int lanehi = lane >> 4;
    const int bsel = lane >> 3;
    const int qrow = warp*16;

    float accS[16][4];
    #pragma unroll
    for (int nt = 0; nt < 16; nt++)
        #pragma unroll
        for (int r = 0; r < 4; r++) accS[nt][r] = 0.f;

    const uint32_t qOff = ((qrow + lane15)*QS_W + lanehi*4)*4;
    uint32_t kOff[8];
    #pragma unroll
    for (int pr = 0; pr < 8; pr++) {
        int krow = pr*16 + (bsel>>1)*8 + (lane & 7);
        kOff[pr] = (krow*QS_W + (bsel & 1)*4)*4;
    }

    #pragma unroll
    for (int ks = 0; ks < 4; ks++) {
        const uint32_t kwB = ks * 32;
        uint32_t a0, a1, a2, a3;
        ldsm4(a0, a1, a2, a3, qBase + qOff + kwB);
        #pragma unroll
        for (int pr = 0; pr < 8; pr++) {
            uint32_t b00, b01, b10, b11;
            ldsm4(b00, b01, b10, b11, kBase + kOff[pr] + kwB);
            mma_f16(accS[pr*2  ], a0, a1, a2, a3, b00, b01);
            mma_f16(accS[pr*2+1], a0, a1, a2, a3, b10, b11);
        }
    }

    const float scale = 0.125f;
    float m0 = -1e30f, m1 = -1e30f;
    #pragma unroll
    for (int nt = 0; nt < 16; nt++) {
        accS[nt][0] *= scale; accS[nt][1] *= scale;
        accS[nt][2] *= scale; accS[nt][3] *= scale;
        m0 = fmaxf(m0, fmaxf(accS[nt][0], accS[nt][1]));
        m1 = fmaxf(m1, fmaxf(accS[nt][2], accS[nt][3]));
    }
    m0 = fmaxf(m0, __shfl_xor_sync(0xffffffff, m0, 1));
    m0 = fmaxf(m0, __shfl_xor_sync(0xffffffff, m0, 2));
    m1 = fmaxf(m1, __shfl_xor_sync(0xffffffff, m1, 1));
    m1 = fmaxf(m1, __shfl_xor_sync(0xffffffff, m1, 2));

    float l0 = 0.f, l1 = 0.f;
    #pragma unroll
    for (int nt = 0; nt < 16; nt++) {
        accS[nt][0] = __expf(accS[nt][0] - m0);
        accS[nt][1] = __expf(accS[nt][1] - m0);
        accS[nt][2] = __expf(accS[nt][2] - m1);
        accS[nt][3] = __expf(accS[nt][3] - m1);
        l0 += accS[nt][0] + accS[nt][1];
        l1 += accS[nt][2] + accS[nt][3];
    }
    l0 += __shfl_xor_sync(0xffffffff, l0, 1);
    l0 += __shfl_xor_sync(0xffffffff, l0, 2);
    l1 += __shfl_xor_sync(0xffffffff, l1, 1);
    l1 += __shfl_xor_sync(0xffffffff, l1, 2);
    float rl0 = 1.f / l0, rl1 = 1.f / l1;

    #pragma unroll
    for (int nt = 0; nt < 16; nt++) {
        __half2 p0 = __float22half2_rn(
            make_float2(accS[nt][0]*rl0, accS[nt][1]*rl0));
        __half2 p1 = __float22half2_rn(
            make_float2(accS[nt][2]*rl1, accS[nt][3]*rl1));
        Psw[(qrow+group  )*VS_W + nt*4 + tid4] = *reinterpret_cast<uint32_t*>(&p0);
        Psw[(qrow+group+8)*VS_W + nt*4 + tid4] = *reinterpret_cast<uint32_t*>(&p1);
    }
    __syncwarp();

    float accO[8][4];
    #pragma unroll
    for (int nt = 0; nt < 8; nt++)
        #pragma unroll
        for (int r = 0; r < 4; r++) accO[nt][r] = 0.f;

    const uint32_t pOff = ((qrow + lane15)*VS_W + lanehi*4)*4;
    uint32_t vOff[4];
    #pragma unroll
    for (int pr = 0; pr < 4; pr++) {
        int drow = pr*16 + (bsel>>1)*8 + (lane & 7);
        vOff[pr] = (drow*VS_W + (bsel & 1)*4)*4;
    }

    #pragma unroll
    for (int ks = 0; ks < 8; ks++) {
        const uint32_t kwB = ks * 32;
        uint32_t a0, a1, a2, a3;
        ldsm4(a0, a1, a2, a3, pBase + pOff + kwB);
        #pragma unroll
        for (int pr = 0; pr < 4; pr++) {
            uint32_t b00, b01, b10, b11;
            ldsm4(b00, b01, b10, b11, vBase + vOff[pr] + kwB);
            mma_f16(accO[pr*2  ], a0, a1, a2, a3, b00, b01);
            mma_f16(accO[pr*2+1], a0, a1, a2, a3, b10, b11);
        }
    }

    long row0 = (long)b*N_ + qb*128 + qrow + group;
    #pragma unroll
    for (int nt = 0; nt < 8; nt++) {
        int col = h*D_ + nt*8 + tid4*2;
        __half2 h0 = __float22half2_rn(make_float2(accO[nt][0], accO[nt][1]));
        __half2 h1 = __float22half2_rn(make_float2(accO[nt][2], accO[nt][3]));
        *reinterpret_cast<__half2*>(O + row0*C_ + col) = h0;
        *reinterpret_cast<__half2*>(O + (row0+8)*C_ + col) = h1;
    }
}

// ---------------------------------------------------------------------------
extern "C" void kernel_launch(void* const* d_in, const int* in_sizes, int n_in,
                              void* d_out, int out_size)
{
    const float* x      = (const float*)d_in[0];
    const float* Wqkv   = (const float*)d_in[1];
    const float* bqkv   = (const float*)d_in[2];
    const float* E_k    = (const float*)d_in[3];
    const float* E_v    = (const float*)d_in[4];
    const float* Wproj  = (const float*)d_in[5];
    const float* bproj  = (const float*)d_in[6];
    const float* k_bank = (const float*)d_in[7];
    const float* v_bank = (const float*)d_in[8];

    __half *xh, *Wqt, *Wpt, *Qh, *xph, *KVh, *kfh, *vth, *ao;
    cudaGetSymbolAddress((void**)&xh,  g_xh);
    cudaGetSymbolAddress((void**)&Wqt, g_Wqt);
    cudaGetSymbolAddress((void**)&Wpt, g_Wpt);
    cudaGetSymbolAddress((void**)&Qh,  g_Qh);
    cudaGetSymbolAddress((void**)&xph, g_xph);
    cudaGetSymbolAddress((void**)&KVh, g_KVh);
    cudaGetSymbolAddress((void**)&kfh, g_kfh);
    cudaGetSymbolAddress((void**)&vth, g_vth);
    cudaGetSymbolAddress((void**)&ao,  g_ao);

    cudaFuncSetAttribute(attn_tc,
                         cudaFuncAttributeMaxDynamicSharedMemorySize, ATTN_SMEM);

    // streams/events (host objects only; leaked by design)
    cudaStream_t s2;
    cudaStreamCreateWithFlags(&s2, cudaStreamNonBlocking);
    cudaEvent_t e0, eW, e2;
    cudaEventCreateWithFlags(&e0, cudaEventDisableTiming);
    cudaEventCreateWithFlags(&eW, cudaEventDisableTiming);
    cudaEventCreateWithFlags(&e2, cudaEventDisableTiming);

    // fork s2
    cudaEventRecord(e0, 0);
    cudaStreamWaitEvent(s2, e0, 0);

    // s2 (fully independent of main until the join):
    //   transposes -> pooled tokens -> KV projection -> compress
    f2h_T<<<dim3(3*C_/32, C_/32), dim3(32, 8), 0, s2>>>(Wqkv, Wqt, C_, 3*C_);
    f2h_T<<<dim3(C_/32, C_/32), dim3(32, 8), 0, s2>>>(Wproj, Wpt, C_, C_);
    cudaEventRecord(eW, s2);
    pool_kernel<<<(B_*L_*C_/4 + 255)/256, 256, 0, s2>>>(x, xph);
    hgemm<<<dim3(2*C_/128, B_*L_/128), 256, 0, s2>>>(
        xph, Wqt + (long)C_*C_, bqkv + C_, KVh, C_, C_, C_, 2*C_, 1);
    kvcompress<<<dim3(2, H_, B_), 128, 0, s2>>>(
        KVh, E_k, E_v, k_bank, v_bank, kfh, vth);
    cudaEventRecord(e2, s2);

    // main: x -> fp16 (MLP=4 streaming convert)
    f2h4<<<B_*N_*C_/4/(256*4), 256>>>(x, xh);

    // main: Q projection (needs Wqt)
    cudaStreamWaitEvent(0, eW, 0);
    hgemm<<<dim3(C_/128, B_*N_/128), 256>>>(xh, Wqt, bqkv, Qh,
                                            C_, C_, C_, C_, 1);

    // join: attention needs kfh/vth
    cudaStreamWaitEvent(0, e2, 0);
    attn_tc<<<dim3(N_/128, H_, B_), 256, ATTN_SMEM>>>(Qh, kfh, vth, ao);

    // out = ao @ Wproj + bproj -> fp32
    hgemm<<<dim3(C_/128, B_*N_/128), 256>>>(ao, Wpt, bproj, (float*)d_out,
                                            C_, C_, C_, C_, 0);
}

// round 16
// speedup vs baseline: 1.0511x; 1.0131x over previous
#include <cuda_runtime.h>
#include <cuda_fp16.h>
#include <math.h>
#include <stdint.h>

#define B_  32
#define N_  1024
#define C_  768
#define H_  12
#define D_  64
#define L_  128

// ---------------- scratch (device globals: no allocations allowed) ----------
__device__ __half g_xh [B_*N_*C_];      // x in fp16
__device__ __half g_Wqt[3*C_*C_];       // Wqkv^T  [2304][768] fp16
__device__ __half g_Wpt[C_*C_];         // Wproj^T [768][768] fp16
__device__ __half g_Qh [B_*N_*C_];      // Q projection, fp16
__device__ __half g_xph[B_*L_*C_];      // pooled tokens, fp16
__device__ __half g_KVh[B_*L_*2*C_];    // K|V projections, fp16
__device__ __half g_kfh[B_*H_*L_*D_];   // k_full fp16 [bh][128][64]
__device__ __half g_vth[B_*H_*D_*L_];   // v_full fp16 TRANSPOSED [bh][64][128]
__device__ __half g_ao [B_*N_*C_];      // attention output, fp16

__device__ __forceinline__ void mma_f16(
    float* c, uint32_t a0, uint32_t a1, uint32_t a2, uint32_t a3,
    uint32_t b0, uint32_t b1)
{
    asm volatile(
        "mma.sync.aligned.m16n8k16.row.col.f32.f16.f16.f32 "
        "{%0,%1,%2,%3}, {%4,%5,%6,%7}, {%8,%9}, {%0,%1,%2,%3};"
        : "+f"(c[0]), "+f"(c[1]), "+f"(c[2]), "+f"(c[3])
        : "r"(a0), "r"(a1), "r"(a2), "r"(a3), "r"(b0), "r"(b1));
}

__device__ __forceinline__ void ldsm4(uint32_t& r0, uint32_t& r1,
                                      uint32_t& r2, uint32_t& r3, uint32_t addr)
{
    asm volatile("ldmatrix.sync.aligned.m8n8.x4.shared.b16 {%0,%1,%2,%3}, [%4];"
                 : "=r"(r0), "=r"(r1), "=r"(r2), "=r"(r3) : "r"(addr));
}

__device__ __forceinline__ void cp16(uint32_t saddr, const void* g) {
    asm volatile("cp.async.ca.shared.global [%0], [%1], 16;"
                 :: "r"(saddr), "l"(g));
}

// ---------------- pure fp32 -> fp16 convert, MLP=4 --------------------------
__global__ void f2h4(const float* __restrict__ s, __half* __restrict__ d)
{
    const long stride = (long)gridDim.x * 256;
    long i0 = (long)blockIdx.x * 256 + threadIdx.x;
    float4 v0 = *reinterpret_cast<const float4*>(s + (i0           )*4);
    float4 v1 = *reinterpret_cast<const float4*>(s + (i0 +   stride)*4);
    float4 v2 = *reinterpret_cast<const float4*>(s + (i0 + 2*stride)*4);
    float4 v3 = *reinterpret_cast<const float4*>(s + (i0 + 3*stride)*4);
    #pragma unroll
    for (int k = 0; k < 4; k++) {
        float4 v = (k==0) ? v0 : (k==1) ? v1 : (k==2) ? v2 : v3;
        __half2 h0 = __float22half2_rn(make_float2(v.x, v.y));
        __half2 h1 = __float22half2_rn(make_float2(v.z, v.w));
        uint2 o;
        o.x = *reinterpret_cast<uint32_t*>(&h0);
        o.y = *reinterpret_cast<uint32_t*>(&h1);
        *reinterpret_cast<uint2*>(d + (i0 + k*stride)*4) = o;
    }
}

// ---------------- pooling -> fp16: xp[b,p,c] = .5*(x[2p]+x[2p+1]) -----------
__global__ void pool_kernel(const float* __restrict__ x, __half* __restrict__ xp)
{
    int i = blockIdx.x * blockDim.x + threadIdx.x;      // 4-elem index
    const int TOT4 = B_*L_*C_/4;
    if (i >= TOT4) return;
    int c4 = i % (C_/4);
    int p  = (i / (C_/4)) % L_;
    int b  = i / (C_/4 * L_);
    long base = (long)b*N_*C_ + (long)(2*p)*C_ + c4*4;
    float4 a = *reinterpret_cast<const float4*>(x + base);
    float4 c = *reinterpret_cast<const float4*>(x + base + C_);
    __half2 h0 = __float22half2_rn(make_float2(0.5f*(a.x+c.x), 0.5f*(a.y+c.y)));
    __half2 h1 = __float22half2_rn(make_float2(0.5f*(a.z+c.z), 0.5f*(a.w+c.w)));
    uint2 o;
    o.x = *reinterpret_cast<uint32_t*>(&h0);
    o.y = *reinterpret_cast<uint32_t*>(&h1);
    *reinterpret_cast<uint2*>(xp + (long)i*4) = o;
}

// ---------------- fp32 -> fp16 transpose: Wt[c][r] = W[r][c] ----------------
__global__ void f2h_T(const float* __restrict__ W, __half* __restrict__ Wt,
                      int rows, int cols)
{
    __shared__ float s[32][33];
    int c0 = blockIdx.x*32, r0 = blockIdx.y*32;
    int tx = threadIdx.x, ty = threadIdx.y;   // 32 x 8
    #pragma unroll
    for (int i = 0; i < 32; i += 8)
        s[ty+i][tx] = W[(long)(r0+ty+i)*cols + c0+tx];
    __syncthreads();
    #pragma unroll
    for (int i = 0; i < 32; i += 8)
        Wt[(long)(c0+ty+i)*rows + r0+tx] = __float2half_rn(s[tx][ty+i]);
}

// -------- fp16 GEMM, cp.async double-buffered, ldmatrix fragments -----------
#define TH_STR 40      // halves per smem row (32 data + 8 pad); 20 words

__global__ __launch_bounds__(256, 2) void hgemm(
    const __half* __restrict__ A, const __half* __restrict__ Bt,
    const float* __restrict__ bias, void* __restrict__ Cv,
    int K, int lda, int ldbt, int ldc, int half_out)
{
    __shared__ __half Ah[2][128*TH_STR];
    __shared__ __half Bh[2][128*TH_STR];

    const int t    = threadIdx.x;
    const int warp = t >> 5;
    const int lane = t & 31;
    const int group = lane >> 2;
    const int tid4  = lane & 3;
    const int wm = (warp & 1) * 64;
    const int wn = (warp >> 1) * 32;

    const int bm = blockIdx.y * 128, bn = blockIdx.x * 128;

    float acc[4][4][4];
    #pragma unroll
    for (int mf = 0; mf < 4; mf++)
        #pragma unroll
        for (int nf = 0; nf < 4; nf++)
            #pragma unroll
            for (int r = 0; r < 4; r++) acc[mf][nf][r] = 0.f;

    const uint32_t aB0 = (uint32_t)__cvta_generic_to_shared(&Ah[0][0]);
    const uint32_t aB1 = (uint32_t)__cvta_generic_to_shared(&Ah[1][0]);
    const uint32_t bB0 = (uint32_t)__cvta_generic_to_shared(&Bh[0][0]);
    const uint32_t bB1 = (uint32_t)__cvta_generic_to_shared(&Bh[1][0]);

    const int lane15 = lane & 15;
    const int lanehi = lane >> 4;
    uint32_t aOff[4];
    #pragma unroll
    for (int mf = 0; mf < 4; mf++)
        aOff[mf] = ((wm + mf*16 + lane15)*20 + lanehi*4)*4;
    const int bsel = lane >> 3;
    uint32_t bOff[2];
    #pragma unroll
    for (int pr = 0; pr < 2; pr++) {
        int row = wn + (pr*2 + (bsel>>1))*8 + (lane & 7);
        bOff[pr] = (row*20 + (bsel & 1)*4)*4;
    }

    const int ar0 = t >> 2,        aof = (t & 3) * 8;
    const int ar1 = ar0 + 64;
    const int br  = t >> 1,        bof = (t & 1) * 16;

    const int ns = K >> 5;

    cp16(aB0 + (ar0*TH_STR + aof)*2, A + (long)(bm + ar0)*lda + aof);
    cp16(aB0 + (ar1*TH_STR + aof)*2, A + (long)(bm + ar1)*lda + aof);
    cp16(bB0 + (br*TH_STR + bof)*2,     Bt + (long)(bn + br)*ldbt + bof);
    cp16(bB0 + (br*TH_STR + bof + 8)*2, Bt + (long)(bn + br)*ldbt + bof + 8);
    asm volatile("cp.async.commit_group;");

    for (int i = 0; i < ns; i++) {
        const int buf = i & 1;
        asm volatile("cp.async.wait_all;" ::: "memory");
        __syncthreads();

        if (i + 1 < ns) {
            const int kn = (i + 1) << 5;
            const uint32_t aB = buf ? aB0 : aB1;
            const uint32_t bB = buf ? bB0 : bB1;
            cp16(aB + (ar0*TH_STR + aof)*2, A + (long)(bm + ar0)*lda + kn + aof);
            cp16(aB + (ar1*TH_STR + aof)*2, A + (long)(bm + ar1)*lda + kn + aof);
            cp16(bB + (br*TH_STR + bof)*2,     Bt + (long)(bn + br)*ldbt + kn + bof);
            cp16(bB + (br*TH_STR + bof + 8)*2, Bt + (long)(bn + br)*ldbt + kn + bof + 8);
            asm volatile("cp.async.commit_group;");
        }

        const uint32_t aB = buf ? aB1 : aB0;
        const uint32_t bB = buf ? bB1 : bB0;

        #pragma unroll
        for (int ks = 0; ks < 2; ks++) {
            const uint32_t kwB = ks * 8 * 4;
            uint32_t a[4][4], b[4][2];
            #pragma unroll
            for (int mf = 0; mf < 4; mf++)
                ldsm4(a[mf][0], a[mf][1], a[mf][2], a[mf][3],
                      aB + aOff[mf] + kwB);
            ldsm4(b[0][0], b[0][1], b[1][0], b[1][1], bB + bOff[0] + kwB);
            ldsm4(b[2][0], b[2][1], b[3][0], b[3][1], bB + bOff[1] + kwB);
            #pragma unroll
            for (int mf = 0; mf < 4; mf++)
                #pragma unroll
                for (int nf = 0; nf < 4; nf++)
                    mma_f16(acc[mf][nf], a[mf][0], a[mf][1], a[mf][2], a[mf][3],
                            b[nf][0], b[nf][1]);
        }
    }

    if (half_out) {
        __half* C = reinterpret_cast<__half*>(Cv);
        #pragma unroll
        for (int mf = 0; mf < 4; mf++) {
            long r0 = bm + wm + mf*16 + group;
            #pragma unroll
            for (int nf = 0; nf < 4; nf++) {
                int c0 = bn + wn + nf*8 + tid4*2;
                float2 bi = *reinterpret_cast<const float2*>(bias + c0);
                __half2 h0 = __float22half2_rn(
                    make_float2(acc[mf][nf][0] + bi.x, acc[mf][nf][1] + bi.y));
                __half2 h1 = __float22half2_rn(
                    make_float2(acc[mf][nf][2] + bi.x, acc[mf][nf][3] + bi.y));
                *reinterpret_cast<__half2*>(C + r0*ldc + c0) = h0;
                *reinterpret_cast<__half2*>(C + (r0+8)*ldc + c0) = h1;
            }
        }
    } else {
        float* C = reinterpret_cast<float*>(Cv);
        #pragma unroll
        for (int mf = 0; mf < 4; mf++) {
            long r0 = bm + wm + mf*16 + group;
            #pragma unroll
            for (int nf = 0; nf < 4; nf++) {
                int c0 = bn + wn + nf*8 + tid4*2;
                float2 bi = *reinterpret_cast<const float2*>(bias + c0);
                float2 o0, o1;
                o0.x = acc[mf][nf][0] + bi.x; o0.y = acc[mf][nf][1] + bi.y;
                o1.x = acc[mf][nf][2] + bi.x; o1.y = acc[mf][nf][3] + bi.y;
                *reinterpret_cast<float2*>(C + r0*ldc + c0) = o0;
                *reinterpret_cast<float2*>(C + (r0+8)*ldc + c0) = o1;
            }
        }
    }
}

// ------ tensor-core kvcompress: out = E^T @ KV_head (64x64x128), + bank -----
__global__ __launch_bounds__(128) void kvcompress(
    const __half* __restrict__ KV, const float* __restrict__ E_k,
    const float* __restrict__ E_v, const float* __restrict__ k_bank,
    const float* __restrict__ v_bank, __half* __restrict__ kf,
    __half* __restrict__ vt)
{
    __shared__ __half Et[64*136];
    __shared__ __half Kt[64*136];

    const int which = blockIdx.x, h = blockIdx.y, b = blockIdx.z;
    const float* E    = which ? E_v : E_k;
    const float* bank = which ? v_bank : k_bank;

    const int t = threadIdx.x;
    const int warp = t >> 5, lane = t & 31;
    const int group = lane >> 2, tid4 = lane & 3;

    for (int i = t*4; i < 128*64; i += 512) {
        int s = i >> 6, c = i & 63;
        float4 v = *reinterpret_cast<const float4*>(E + s*64 + c);
        Et[(c+0)*136 + s] = __float2half_rn(v.x);
        Et[(c+1)*136 + s] = __float2half_rn(v.y);
        Et[(c+2)*136 + s] = __float2half_rn(v.z);
        Et[(c+3)*136 + s] = __float2half_rn(v.w);
    }
    const __half* kvp = KV + (long)b*L_*2*C_ + which*C_ + h*D_;
    for (int i = t*4; i < 128*64; i += 512) {
        int s = i >> 6, d = i & 63;
        uint2 raw = *reinterpret_cast<const uint2*>(kvp + (long)s*2*C_ + d);
        const __half* hp = reinterpret_cast<const __half*>(&raw);
        Kt[(d+0)*136 + s] = hp[0];
        Kt[(d+1)*136 + s] = hp[1];
        Kt[(d+2)*136 + s] = hp[2];
        Kt[(d+3)*136 + s] = hp[3];
    }
    __syncthreads();

    float acc[8][4];
    #pragma unroll
    for (int nf = 0; nf < 8; nf++)
        #pragma unroll
        for (int r = 0; r < 4; r++) acc[nf][r] = 0.f;

    const uint32_t* Ew = reinterpret_cast<const uint32_t*>(Et);
    const uint32_t* Kw = reinterpret_cast<const uint32_t*>(Kt);
    const int m0 = warp*16 + group;

    #pragma unroll
    for (int ks = 0; ks < 8; ks++) {
        const int kw = ks * 8;
        uint32_t a0 = Ew[(m0    )*68 + kw + tid4];
        uint32_t a1 = Ew[(m0 + 8)*68 + kw + tid4];
        uint32_t a2 = Ew[(m0    )*68 + kw + tid4 + 4];
        uint32_t a3 = Ew[(m0 + 8)*68 + kw + tid4 + 4];
        #pragma unroll
        for (int nf = 0; nf < 8; nf++) {
            uint32_t b0 = Kw[(nf*8+group)*68 + kw + tid4];
            uint32_t b1 = Kw[(nf*8+group)*68 + kw + tid4 + 4];
            mma_f16(acc[nf], a0, a1, a2, a3, b0, b1);
        }
    }

    const long bh = (long)(b*H_ + h);
    if (which == 0) {
        __half* out = kf + bh*L_*D_;
        #pragma unroll
        for (int nf = 0; nf < 8; nf++) {
            int d = nf*8 + tid4*2;
            __half2 h0 = __float22half2_rn(make_float2(acc[nf][0], acc[nf][1]));
            __half2 h1 = __float22half2_rn(make_float2(acc[nf][2], acc[nf][3]));
            *reinterpret_cast<__half2*>(out + (m0  )*64 + d) = h0;
            *reinterpret_cast<__half2*>(out + (m0+8)*64 + d) = h1;
        }
        __syncthreads();
        for (int i = t*4; i < 64*64; i += 512) {
            int r = i >> 6, d = i & 63;
            float4 v = *reinterpret_cast<const float4*>(
                bank + (long)b*64*C_ + (long)r*C_ + h*D_ + d);
            __half2 h0 = __float22half2_rn(make_float2(v.x, v.y));
            __half2 h1 = __float22half2_rn(make_float2(v.z, v.w));
            *reinterpret_cast<__half2*>(out + (64+r)*64 + d) = h0;
            *reinterpret_cast<__half2*>(out + (64+r)*64 + d + 2) = h1;
        }
    } else {
        __half* out = vt + bh*D_*L_;
        #pragma unroll
        for (int nf = 0; nf < 8; nf++) {
            int d = nf*8 + tid4*2;
            out[(d  )*128 + m0    ] = __float2half_rn(acc[nf][0]);
            out[(d+1)*128 + m0    ] = __float2half_rn(acc[nf][1]);
            out[(d  )*128 + m0 + 8] = __float2half_rn(acc[nf][2]);
            out[(d+1)*128 + m0 + 8] = __float2half_rn(acc[nf][3]);
        }
        __syncthreads();
        for (int i = t*4; i < 64*64; i += 512) {
            int r = i >> 6, d = i & 63;
            float4 v = *reinterpret_cast<const float4*>(
                bank + (long)b*64*C_ + (long)r*C_ + h*D_ + d);
            out[(d  )*128 + 64 + r] = __float2half_rn(v.x);
            out[(d+1)*128 + 64 + r] = __float2half_rn(v.y);
            out[(d+2)*128 + 64 + r] = __float2half_rn(v.z);
            out[(d+3)*128 + 64 + r] = __float2half_rn(v.w);
        }
    }
}

// -------- fp16 tensor-core attention; P kept in registers -------------------
// S accumulator (m16n8 f32) reinterpreted directly as PV A-fragments.
#define QS_W 36
#define VS_W 68
#define ATTN_SMEM ((128*QS_W + 64*VS_W + 128*QS_W) * 4)

__global__ __launch_bounds__(256, 2) void attn_tc(
    const __half* __restrict__ Q, const __half* __restrict__ kf,
    const __half* __restrict__ vt, __half* __restrict__ O)
{
    extern __shared__ uint32_t smu[];
    uint32_t* Ksw = smu;                      // [128][36]
    uint32_t* Vtw = Ksw + 128*QS_W;           // [64][68]
    uint32_t* Qsw = Vtw + 64*VS_W;            // [128][36]

    const int t = threadIdx.x;
    const int warp = t >> 5, lane = t & 31;
    const int group = lane >> 2, tid4 = lane & 3;
    const int qb = blockIdx.x, h = blockIdx.y, b = blockIdx.z;

    const __half* kfp = kf + (long)(b*H_ + h) * L_ * D_;
    const __half* vtp = vt + (long)(b*H_ + h) * D_ * L_;

    for (int i = t*8; i < L_*D_; i += 2048) {
        int k = i >> 6, d = i & 63;
        *reinterpret_cast<uint4*>(&Ksw[k*QS_W + (d>>1)]) =
            *reinterpret_cast<const uint4*>(kfp + i);
    }
    for (int i = t*8; i < D_*L_; i += 2048) {
        int d = i >> 7, k = i & 127;
        *reinterpret_cast<uint4*>(&Vtw[d*VS_W + (k>>1)]) =
            *reinterpret_cast<const uint4*>(vtp + i);
    }
    {
        long base = ((long)b*N_ + qb*128) * C_ + h*D_;
        for (int i = t*8; i < 128*64; i += 2048) {
            int q = i >> 6, d = i & 63;
            *reinterpret_cast<uint4*>(&Qsw[q*QS_W + (d>>1)]) =
                *reinterpret_cast<const uint4*>(Q + base + (long)q*C_ + d);
        }
    }
    __syncthreads();

    const uint32_t kBase = (uint32_t)__cvta_generic_to_shared(Ksw);
    const uint32_t vBase = (uint32_t)__cvta_generic_to_shared(Vtw);
    const uint32_t qBase = (uint32_t)__cvta_generic_to_shared(Qsw);

    const int lane15 = lane & 15;
    const int lanehi = lane >> 4;
    const int bsel = lane >> 3;
    const int qrow = warp*16;

    // --- S = Q K^T ---
    float accS[16][4];
    #pragma unroll
    for (int nt = 0; nt < 16; nt++)
        #pragma unroll
        for (int r = 0; r < 4; r++) accS[nt][r] = 0.f;

    const uint32_t qOff = ((qrow + lane15)*QS_W + lanehi*4)*4;
    uint32_t kOff[8];
    #pragma unroll
    for (int pr = 0; pr < 8; pr++) {
        int krow = pr*16 + (bsel>>1)*8 + (lane & 7);
        kOff[pr] = (krow*QS_W + (bsel & 1)*4)*4;
    }

    #pragma unroll
    for (int ks = 0; ks < 4; ks++) {
        const uint32_t kwB = ks * 32;
        uint32_t a0, a1, a2, a3;
        ldsm4(a0, a1, a2, a3, qBase + qOff + kwB);
        #pragma unroll
        for (int pr = 0; pr < 8; pr++) {
            uint32_t b00, b01, b10, b11;
            ldsm4(b00, b01, b10, b11, kBase + kOff[pr] + kwB);
            mma_f16(accS[pr*2  ], a0, a1, a2, a3, b00, b01);
            mma_f16(accS[pr*2+1], a0, a1, a2, a3, b10, b11);
        }
    }

    // --- softmax over 128 keys ---
    const float scale = 0.125f;
    float m0 = -1e30f, m1 = -1e30f;
    #pragma unroll
    for (int nt = 0; nt < 16; nt++) {
        accS[nt][0] *= scale; accS[nt][1] *= scale;
        accS[nt][2] *= scale; accS[nt][3] *= scale;
        m0 = fmaxf(m0, fmaxf(accS[nt][0], accS[nt][1]));
        m1 = fmaxf(m1, fmaxf(accS[nt][2], accS[nt][3]));
    }
    m0 = fmaxf(m0, __shfl_xor_sync(0xffffffff, m0, 1));
    m0 = fmaxf(m0, __shfl_xor_sync(0xffffffff, m0, 2));
    m1 = fmaxf(m1, __shfl_xor_sync(0xffffffff, m1, 1));
    m1 = fmaxf(m1, __shfl_xor_sync(0xffffffff, m1, 2));

    float l0 = 0.f, l1 = 0.f;
    #pragma unroll
    for (int nt = 0; nt < 16; nt++) {
        accS[nt][0] = __expf(accS[nt][0] - m0);
        accS[nt][1] = __expf(accS[nt][1] - m0);
        accS[nt][2] = __expf(accS[nt][2] - m1);
        accS[nt][3] = __expf(accS[nt][3] - m1);
        l0 += accS[nt][0] + accS[nt][1];
        l1 += accS[nt][2] + accS[nt][3];
    }
    l0 += __shfl_xor_sync(0xffffffff, l0, 1);
    l0 += __shfl_xor_sync(0xffffffff, l0, 2);
    l1 += __shfl_xor_sync(0xffffffff, l1, 1);
    l1 += __shfl_xor_sync(0xffffffff, l1, 2);
    float rl0 = 1.f / l0, rl1 = 1.f / l1;

    // --- pack normalized P directly into PV A-fragments (register-resident).
    // m16n8 C layout == m16k16 A layout: for k16-chunk ks (S tiles 2ks, 2ks+1):
    //   a0 = (row group,   keys 16ks+2tid4..+1) = accS[2ks][0..1]*rl0
    //   a1 = (row group+8, same keys)           = accS[2ks][2..3]*rl1
    //   a2 = (row group,   keys +8)             = accS[2ks+1][0..1]*rl0
    //   a3 = (row group+8, keys +8)             = accS[2ks+1][2..3]*rl1
    uint32_t pfrag[8][4];
    #pragma unroll
    for (int ks = 0; ks < 8; ks++) {
        __half2 f0 = __float22half2_rn(
            make_float2(accS[2*ks  ][0]*rl0, accS[2*ks  ][1]*rl0));
        __half2 f1 = __float22half2_rn(
            make_float2(accS[2*ks  ][2]*rl1, accS[2*ks  ][3]*rl1));
        __half2 f2 = __float22half2_rn(
            make_float2(accS[2*ks+1][0]*rl0, accS[2*ks+1][1]*rl0));
        __half2 f3 = __float22half2_rn(
            make_float2(accS[2*ks+1][2]*rl1, accS[2*ks+1][3]*rl1));
        pfrag[ks][0] = *reinterpret_cast<uint32_t*>(&f0);
        pfrag[ks][1] = *reinterpret_cast<uint32_t*>(&f1);
        pfrag[ks][2] = *reinterpret_cast<uint32_t*>(&f2);
        pfrag[ks][3] = *reinterpret_cast<uint32_t*>(&f3);
    }

    // --- O = P V ---
    float accO[8][4];
    #pragma unroll
    for (int nt = 0; nt < 8; nt++)
        #pragma unroll
        for (int r = 0; r < 4; r++) accO[nt][r] = 0.f;

    uint32_t vOff[4];
    #pragma unroll
    for (int pr = 0; pr < 4; pr++) {
        int drow = pr*16 + (bsel>>1)*8 + (lane & 7);
        vOff[pr] = (drow*VS_W + (bsel & 1)*4)*4;
    }

    #pragma unroll
    for (int ks = 0; ks < 8; ks++) {
        const uint32_t kwB = ks * 32;
        #pragma unroll
        for (int pr = 0; pr < 4; pr++) {
            uint32_t b00, b01, b10, b11;
            ldsm4(b00, b01, b10, b11, vBase + vOff[pr] + kwB);
            mma_f16(accO[pr*2  ], pfrag[ks][0], pfrag[ks][1],
                    pfrag[ks][2], pfrag[ks][3], b00, b01);
            mma_f16(accO[pr*2+1], pfrag[ks][0], pfrag[ks][1],
                    pfrag[ks][2], pfrag[ks][3], b10, b11);
        }
    }

    long row0 = (long)b*N_ + qb*128 + qrow + group;
    #pragma unroll
    for (int nt = 0; nt < 8; nt++) {
        int col = h*D_ + nt*8 + tid4*2;
        __half2 h0 = __float22half2_rn(make_float2(accO[nt][0], accO[nt][1]));
        __half2 h1 = __float22half2_rn(make_float2(accO[nt][2], accO[nt][3]));
        *reinterpret_cast<__half2*>(O + row0*C_ + col) = h0;
        *reinterpret_cast<__half2*>(O + (row0+8)*C_ + col) = h1;
    }
}

// ---------------------------------------------------------------------------
extern "C" void kernel_launch(void* const* d_in, const int* in_sizes, int n_in,
                              void* d_out, int out_size)
{
    const float* x      = (const float*)d_in[0];
    const float* Wqkv   = (const float*)d_in[1];
    const float* bqkv   = (const float*)d_in[2];
    const float* E_k    = (const float*)d_in[3];
    const float* E_v    = (const float*)d_in[4];
    const float* Wproj  = (const float*)d_in[5];
    const float* bproj  = (const float*)d_in[6];
    const float* k_bank = (const float*)d_in[7];
    const float* v_bank = (const float*)d_in[8];

    __half *xh, *Wqt, *Wpt, *Qh, *xph, *KVh, *kfh, *vth, *ao;
    cudaGetSymbolAddress((void**)&xh,  g_xh);
    cudaGetSymbolAddress((void**)&Wqt, g_Wqt);
    cudaGetSymbolAddress((void**)&Wpt, g_Wpt);
    cudaGetSymbolAddress((void**)&Qh,  g_Qh);
    cudaGetSymbolAddress((void**)&xph, g_xph);
    cudaGetSymbolAddress((void**)&KVh, g_KVh);
    cudaGetSymbolAddress((void**)&kfh, g_kfh);
    cudaGetSymbolAddress((void**)&vth, g_vth);
    cudaGetSymbolAddress((void**)&ao,  g_ao);

    cudaFuncSetAttribute(attn_tc,
                         cudaFuncAttributeMaxDynamicSharedMemorySize, ATTN_SMEM);

    // streams/events (host objects only; leaked by design)
    cudaStream_t s2;
    cudaStreamCreateWithFlags(&s2, cudaStreamNonBlocking);
    cudaEvent_t e0, eW, e2;
    cudaEventCreateWithFlags(&e0, cudaEventDisableTiming);
    cudaEventCreateWithFlags(&eW, cudaEventDisableTiming);
    cudaEventCreateWithFlags(&e2, cudaEventDisableTiming);

    // fork s2
    cudaEventRecord(e0, 0);
    cudaStreamWaitEvent(s2, e0, 0);

    // s2: transposes -> pooled tokens -> KV projection -> compress
    f2h_T<<<dim3(3*C_/32, C_/32), dim3(32, 8), 0, s2>>>(Wqkv, Wqt, C_, 3*C_);
    f2h_T<<<dim3(C_/32, C_/32), dim3(32, 8), 0, s2>>>(Wproj, Wpt, C_, C_);
    cudaEventRecord(eW, s2);
    pool_kernel<<<(B_*L_*C_/4 + 255)/256, 256, 0, s2>>>(x, xph);
    hgemm<<<dim3(2*C_/128, B_*L_/128), 256, 0, s2>>>(
        xph, Wqt + (long)C_*C_, bqkv + C_, KVh, C_, C_, C_, 2*C_, 1);
    kvcompress<<<dim3(2, H_, B_), 128, 0, s2>>>(
        KVh, E_k, E_v, k_bank, v_bank, kfh, vth);
    cudaEventRecord(e2, s2);

    // main: x -> fp16
    f2h4<<<B_*N_*C_/4/(256*4), 256>>>(x, xh);

    // main: Q projection (needs Wqt)
    cudaStreamWaitEvent(0, eW, 0);
    hgemm<<<dim3(C_/128, B_*N_/128), 256>>>(xh, Wqt, bqkv, Qh,
                                            C_, C_, C_, C_, 1);

    // join: attention needs kfh/vth
    cudaStreamWaitEvent(0, e2, 0);
    attn_tc<<<dim3(N_/128, H_, B_), 256, ATTN_SMEM>>>(Qh, kfh, vth, ao);

    // out = ao @ Wproj + bproj -> fp32
    hgemm<<<dim3(C_/128, B_*N_/128), 256>>>(ao, Wpt, bproj, (float*)d_out,
                                            C_, C_, C_, C_, 0);
}

// round 17
// speedup vs baseline: 1.0672x; 1.0154x over previous
#include <cuda_runtime.h>
#include <cuda_fp16.h>
#include <math.h>
#include <stdint.h>

#define B_  32
#define N_  1024
#define C_  768
#define H_  12
#define D_  64
#define L_  128

// ---------------- scratch (device globals: no allocations allowed) ----------
__device__ __half g_xh [B_*N_*C_];      // x in fp16
__device__ __half g_Wqt[3*C_*C_];       // Wqkv^T  [2304][768] fp16
__device__ __half g_Wpt[C_*C_];         // Wproj^T [768][768] fp16
__device__ __half g_Qh [B_*N_*C_];      // Q projection, fp16
__device__ __half g_xph[B_*L_*C_];      // pooled tokens, fp16
__device__ __half g_KVh[B_*L_*2*C_];    // K|V projections, fp16
__device__ __half g_kfh[B_*H_*L_*D_];   // k_full fp16 [bh][128][64]
__device__ __half g_vth[B_*H_*D_*L_];   // v_full fp16 TRANSPOSED [bh][64][128]
__device__ __half g_ao [B_*N_*C_];      // attention output, fp16

__device__ __forceinline__ void mma_f16(
    float* c, uint32_t a0, uint32_t a1, uint32_t a2, uint32_t a3,
    uint32_t b0, uint32_t b1)
{
    asm volatile(
        "mma.sync.aligned.m16n8k16.row.col.f32.f16.f16.f32 "
        "{%0,%1,%2,%3}, {%4,%5,%6,%7}, {%8,%9}, {%0,%1,%2,%3};"
        : "+f"(c[0]), "+f"(c[1]), "+f"(c[2]), "+f"(c[3])
        : "r"(a0), "r"(a1), "r"(a2), "r"(a3), "r"(b0), "r"(b1));
}

__device__ __forceinline__ void ldsm4(uint32_t& r0, uint32_t& r1,
                                      uint32_t& r2, uint32_t& r3, uint32_t addr)
{
    asm volatile("ldmatrix.sync.aligned.m8n8.x4.shared.b16 {%0,%1,%2,%3}, [%4];"
                 : "=r"(r0), "=r"(r1), "=r"(r2), "=r"(r3) : "r"(addr));
}

__device__ __forceinline__ void cp16(uint32_t saddr, const void* g) {
    asm volatile("cp.async.ca.shared.global [%0], [%1], 16;"
                 :: "r"(saddr), "l"(g));
}

// ---------------- pure fp32 -> fp16 convert, MLP=4 --------------------------
__global__ void f2h4(const float* __restrict__ s, __half* __restrict__ d)
{
    const long stride = (long)gridDim.x * 256;
    long i0 = (long)blockIdx.x * 256 + threadIdx.x;
    float4 v0 = *reinterpret_cast<const float4*>(s + (i0           )*4);
    float4 v1 = *reinterpret_cast<const float4*>(s + (i0 +   stride)*4);
    float4 v2 = *reinterpret_cast<const float4*>(s + (i0 + 2*stride)*4);
    float4 v3 = *reinterpret_cast<const float4*>(s + (i0 + 3*stride)*4);
    #pragma unroll
    for (int k = 0; k < 4; k++) {
        float4 v = (k==0) ? v0 : (k==1) ? v1 : (k==2) ? v2 : v3;
        __half2 h0 = __float22half2_rn(make_float2(v.x, v.y));
        __half2 h1 = __float22half2_rn(make_float2(v.z, v.w));
        uint2 o;
        o.x = *reinterpret_cast<uint32_t*>(&h0);
        o.y = *reinterpret_cast<uint32_t*>(&h1);
        *reinterpret_cast<uint2*>(d + (i0 + k*stride)*4) = o;
    }
}

// ---------------- pooling -> fp16: xp[b,p,c] = .5*(x[2p]+x[2p+1]) -----------
__global__ void pool_kernel(const float* __restrict__ x, __half* __restrict__ xp)
{
    int i = blockIdx.x * blockDim.x + threadIdx.x;      // 4-elem index
    const int TOT4 = B_*L_*C_/4;
    if (i >= TOT4) return;
    int c4 = i % (C_/4);
    int p  = (i / (C_/4)) % L_;
    int b  = i / (C_/4 * L_);
    long base = (long)b*N_*C_ + (long)(2*p)*C_ + c4*4;
    float4 a = *reinterpret_cast<const float4*>(x + base);
    float4 c = *reinterpret_cast<const float4*>(x + base + C_);
    __half2 h0 = __float22half2_rn(make_float2(0.5f*(a.x+c.x), 0.5f*(a.y+c.y)));
    __half2 h1 = __float22half2_rn(make_float2(0.5f*(a.z+c.z), 0.5f*(a.w+c.w)));
    uint2 o;
    o.x = *reinterpret_cast<uint32_t*>(&h0);
    o.y = *reinterpret_cast<uint32_t*>(&h1);
    *reinterpret_cast<uint2*>(xp + (long)i*4) = o;
}

// ---------------- fp32 -> fp16 transpose: Wt[c][r] = W[r][c] ----------------
__global__ void f2h_T(const float* __restrict__ W, __half* __restrict__ Wt,
                      int rows, int cols)
{
    __shared__ float s[32][33];
    int c0 = blockIdx.x*32, r0 = blockIdx.y*32;
    int tx = threadIdx.x, ty = threadIdx.y;   // 32 x 8
    #pragma unroll
    for (int i = 0; i < 32; i += 8)
        s[ty+i][tx] = W[(long)(r0+ty+i)*cols + c0+tx];
    __syncthreads();
    #pragma unroll
    for (int i = 0; i < 32; i += 8)
        Wt[(long)(c0+ty+i)*rows + r0+tx] = __float2half_rn(s[tx][ty+i]);
}

// -------- fp16 GEMM, cp.async double-buffered, ldmatrix fragments -----------
#define TH_STR 40      // halves per smem row (32 data + 8 pad); 20 words

__global__ __launch_bounds__(256, 2) void hgemm(
    const __half* __restrict__ A, const __half* __restrict__ Bt,
    const float* __restrict__ bias, void* __restrict__ Cv,
    int K, int lda, int ldbt, int ldc, int half_out)
{
    __shared__ __half Ah[2][128*TH_STR];
    __shared__ __half Bh[2][128*TH_STR];

    const int t    = threadIdx.x;
    const int warp = t >> 5;
    const int lane = t & 31;
    const int group = lane >> 2;
    const int tid4  = lane & 3;
    const int wm = (warp & 1) * 64;
    const int wn = (warp >> 1) * 32;

    const int bm = blockIdx.y * 128, bn = blockIdx.x * 128;

    float acc[4][4][4];
    #pragma unroll
    for (int mf = 0; mf < 4; mf++)
        #pragma unroll
        for (int nf = 0; nf < 4; nf++)
            #pragma unroll
            for (int r = 0; r < 4; r++) acc[mf][nf][r] = 0.f;

    const uint32_t aB0 = (uint32_t)__cvta_generic_to_shared(&Ah[0][0]);
    const uint32_t aB1 = (uint32_t)__cvta_generic_to_shared(&Ah[1][0]);
    const uint32_t bB0 = (uint32_t)__cvta_generic_to_shared(&Bh[0][0]);
    const uint32_t bB1 = (uint32_t)__cvta_generic_to_shared(&Bh[1][0]);

    const int lane15 = lane & 15;
    const int lanehi = lane >> 4;
    uint32_t aOff[4];
    #pragma unroll
    for (int mf = 0; mf < 4; mf++)
        aOff[mf] = ((wm + mf*16 + lane15)*20 + lanehi*4)*4;
    const int bsel = lane >> 3;
    uint32_t bOff[2];
    #pragma unroll
    for (int pr = 0; pr < 2; pr++) {
        int row = wn + (pr*2 + (bsel>>1))*8 + (lane & 7);
        bOff[pr] = (row*20 + (bsel & 1)*4)*4;
    }

    const int ar0 = t >> 2,        aof = (t & 3) * 8;
    const int ar1 = ar0 + 64;
    const int br  = t >> 1,        bof = (t & 1) * 16;

    const int ns = K >> 5;

    cp16(aB0 + (ar0*TH_STR + aof)*2, A + (long)(bm + ar0)*lda + aof);
    cp16(aB0 + (ar1*TH_STR + aof)*2, A + (long)(bm + ar1)*lda + aof);
    cp16(bB0 + (br*TH_STR + bof)*2,     Bt + (long)(bn + br)*ldbt + bof);
    cp16(bB0 + (br*TH_STR + bof + 8)*2, Bt + (long)(bn + br)*ldbt + bof + 8);
    asm volatile("cp.async.commit_group;");

    for (int i = 0; i < ns; i++) {
        const int buf = i & 1;
        asm volatile("cp.async.wait_all;" ::: "memory");
        __syncthreads();

        if (i + 1 < ns) {
            const int kn = (i + 1) << 5;
            const uint32_t aB = buf ? aB0 : aB1;
            const uint32_t bB = buf ? bB0 : bB1;
            cp16(aB + (ar0*TH_STR + aof)*2, A + (long)(bm + ar0)*lda + kn + aof);
            cp16(aB + (ar1*TH_STR + aof)*2, A + (long)(bm + ar1)*lda + kn + aof);
            cp16(bB + (br*TH_STR + bof)*2,     Bt + (long)(bn + br)*ldbt + kn + bof);
            cp16(bB + (br*TH_STR + bof + 8)*2, Bt + (long)(bn + br)*ldbt + kn + bof + 8);
            asm volatile("cp.async.commit_group;");
        }

        const uint32_t aB = buf ? aB1 : aB0;
        const uint32_t bB = buf ? bB1 : bB0;

        #pragma unroll
        for (int ks = 0; ks < 2; ks++) {
            const uint32_t kwB = ks * 8 * 4;
            uint32_t a[4][4], b[4][2];
            #pragma unroll
            for (int mf = 0; mf < 4; mf++)
                ldsm4(a[mf][0], a[mf][1], a[mf][2], a[mf][3],
                      aB + aOff[mf] + kwB);
            ldsm4(b[0][0], b[0][1], b[1][0], b[1][1], bB + bOff[0] + kwB);
            ldsm4(b[2][0], b[2][1], b[3][0], b[3][1], bB + bOff[1] + kwB);
            #pragma unroll
            for (int mf = 0; mf < 4; mf++)
                #pragma unroll
                for (int nf = 0; nf < 4; nf++)
                    mma_f16(acc[mf][nf], a[mf][0], a[mf][1], a[mf][2], a[mf][3],
                            b[nf][0], b[nf][1]);
        }
    }

    if (half_out) {
        __half* C = reinterpret_cast<__half*>(Cv);
        #pragma unroll
        for (int mf = 0; mf < 4; mf++) {
            long r0 = bm + wm + mf*16 + group;
            #pragma unroll
            for (int nf = 0; nf < 4; nf++) {
                int c0 = bn + wn + nf*8 + tid4*2;
                float2 bi = *reinterpret_cast<const float2*>(bias + c0);
                __half2 h0 = __float22half2_rn(
                    make_float2(acc[mf][nf][0] + bi.x, acc[mf][nf][1] + bi.y));
                __half2 h1 = __float22half2_rn(
                    make_float2(acc[mf][nf][2] + bi.x, acc[mf][nf][3] + bi.y));
                *reinterpret_cast<__half2*>(C + r0*ldc + c0) = h0;
                *reinterpret_cast<__half2*>(C + (r0+8)*ldc + c0) = h1;
            }
        }
    } else {
        float* C = reinterpret_cast<float*>(Cv);
        #pragma unroll
        for (int mf = 0; mf < 4; mf++) {
            long r0 = bm + wm + mf*16 + group;
            #pragma unroll
            for (int nf = 0; nf < 4; nf++) {
                int c0 = bn + wn + nf*8 + tid4*2;
                float2 bi = *reinterpret_cast<const float2*>(bias + c0);
                float2 o0, o1;
                o0.x = acc[mf][nf][0] + bi.x; o0.y = acc[mf][nf][1] + bi.y;
                o1.x = acc[mf][nf][2] + bi.x; o1.y = acc[mf][nf][3] + bi.y;
                *reinterpret_cast<float2*>(C + r0*ldc + c0) = o0;
                *reinterpret_cast<float2*>(C + (r0+8)*ldc + c0) = o1;
            }
        }
    }
}

// ------ tensor-core kvcompress: out = E^T @ KV_head (64x64x128), + bank -----
__global__ __launch_bounds__(128) void kvcompress(
    const __half* __restrict__ KV, const float* __restrict__ E_k,
    const float* __restrict__ E_v, const float* __restrict__ k_bank,
    const float* __restrict__ v_bank, __half* __restrict__ kf,
    __half* __restrict__ vt)
{
    __shared__ __half Et[64*136];
    __shared__ __half Kt[64*136];

    const int which = blockIdx.x, h = blockIdx.y, b = blockIdx.z;
    const float* E    = which ? E_v : E_k;
    const float* bank = which ? v_bank : k_bank;

    const int t = threadIdx.x;
    const int warp = t >> 5, lane = t & 31;
    const int group = lane >> 2, tid4 = lane & 3;

    for (int i = t*4; i < 128*64; i += 512) {
        int s = i >> 6, c = i & 63;
        float4 v = *reinterpret_cast<const float4*>(E + s*64 + c);
        Et[(c+0)*136 + s] = __float2half_rn(v.x);
        Et[(c+1)*136 + s] = __float2half_rn(v.y);
        Et[(c+2)*136 + s] = __float2half_rn(v.z);
        Et[(c+3)*136 + s] = __float2half_rn(v.w);
    }
    const __half* kvp = KV + (long)b*L_*2*C_ + which*C_ + h*D_;
    for (int i = t*4; i < 128*64; i += 512) {
        int s = i >> 6, d = i & 63;
        uint2 raw = *reinterpret_cast<const uint2*>(kvp + (long)s*2*C_ + d);
        const __half* hp = reinterpret_cast<const __half*>(&raw);
        Kt[(d+0)*136 + s] = hp[0];
        Kt[(d+1)*136 + s] = hp[1];
        Kt[(d+2)*136 + s] = hp[2];
        Kt[(d+3)*136 + s] = hp[3];
    }
    __syncthreads();

    float acc[8][4];
    #pragma unroll
    for (int nf = 0; nf < 8; nf++)
        #pragma unroll
        for (int r = 0; r < 4; r++) acc[nf][r] = 0.f;

    const uint32_t* Ew = reinterpret_cast<const uint32_t*>(Et);
    const uint32_t* Kw = reinterpret_cast<const uint32_t*>(Kt);
    const int m0 = warp*16 + group;

    #pragma unroll
    for (int ks = 0; ks < 8; ks++) {
        const int kw = ks * 8;
        uint32_t a0 = Ew[(m0    )*68 + kw + tid4];
        uint32_t a1 = Ew[(m0 + 8)*68 + kw + tid4];
        uint32_t a2 = Ew[(m0    )*68 + kw + tid4 + 4];
        uint32_t a3 = Ew[(m0 + 8)*68 + kw + tid4 + 4];
        #pragma unroll
        for (int nf = 0; nf < 8; nf++) {
            uint32_t b0 = Kw[(nf*8+group)*68 + kw + tid4];
            uint32_t b1 = Kw[(nf*8+group)*68 + kw + tid4 + 4];
            mma_f16(acc[nf], a0, a1, a2, a3, b0, b1);
        }
    }

    const long bh = (long)(b*H_ + h);
    if (which == 0) {
        __half* out = kf + bh*L_*D_;
        #pragma unroll
        for (int nf = 0; nf < 8; nf++) {
            int d = nf*8 + tid4*2;
            __half2 h0 = __float22half2_rn(make_float2(acc[nf][0], acc[nf][1]));
            __half2 h1 = __float22half2_rn(make_float2(acc[nf][2], acc[nf][3]));
            *reinterpret_cast<__half2*>(out + (m0  )*64 + d) = h0;
            *reinterpret_cast<__half2*>(out + (m0+8)*64 + d) = h1;
        }
        __syncthreads();
        for (int i = t*4; i < 64*64; i += 512) {
            int r = i >> 6, d = i & 63;
            float4 v = *reinterpret_cast<const float4*>(
                bank + (long)b*64*C_ + (long)r*C_ + h*D_ + d);
            __half2 h0 = __float22half2_rn(make_float2(v.x, v.y));
            __half2 h1 = __float22half2_rn(make_float2(v.z, v.w));
            *reinterpret_cast<__half2*>(out + (64+r)*64 + d) = h0;
            *reinterpret_cast<__half2*>(out + (64+r)*64 + d + 2) = h1;
        }
    } else {
        __half* out = vt + bh*D_*L_;
        #pragma unroll
        for (int nf = 0; nf < 8; nf++) {
            int d = nf*8 + tid4*2;
            out[(d  )*128 + m0    ] = __float2half_rn(acc[nf][0]);
            out[(d+1)*128 + m0    ] = __float2half_rn(acc[nf][1]);
            out[(d  )*128 + m0 + 8] = __float2half_rn(acc[nf][2]);
            out[(d+1)*128 + m0 + 8] = __float2half_rn(acc[nf][3]);
        }
        __syncthreads();
        for (int i = t*4; i < 64*64; i += 512) {
            int r = i >> 6, d = i & 63;
            float4 v = *reinterpret_cast<const float4*>(
                bank + (long)b*64*C_ + (long)r*C_ + h*D_ + d);
            out[(d  )*128 + 64 + r] = __float2half_rn(v.x);
            out[(d+1)*128 + 64 + r] = __float2half_rn(v.y);
            out[(d+2)*128 + 64 + r] = __float2half_rn(v.z);
            out[(d+3)*128 + 64 + r] = __float2half_rn(v.w);
        }
    }
}

// -------- fp16 tensor-core attention; P in registers; 2 q-tiles/block -------
#define QS_W 36
#define VS_W 68
#define ATTN_SMEM ((128*QS_W + 64*VS_W + 128*QS_W) * 4)

__global__ __launch_bounds__(256, 2) void attn_tc(
    const __half* __restrict__ Q, const __half* __restrict__ kf,
    const __half* __restrict__ vt, __half* __restrict__ O)
{
    extern __shared__ uint32_t smu[];
    uint32_t* Ksw = smu;                      // [128][36]
    uint32_t* Vtw = Ksw + 128*QS_W;           // [64][68]
    uint32_t* Qsw = Vtw + 64*VS_W;            // [128][36]

    const int t = threadIdx.x;
    const int warp = t >> 5, lane = t & 31;
    const int group = lane >> 2, tid4 = lane & 3;
    const int qb2 = blockIdx.x, h = blockIdx.y, b = blockIdx.z;

    const __half* kfp = kf + (long)(b*H_ + h) * L_ * D_;
    const __half* vtp = vt + (long)(b*H_ + h) * D_ * L_;

    // K / V loaded once per (b,h) pair of q-tiles
    for (int i = t*8; i < L_*D_; i += 2048) {
        int k = i >> 6, d = i & 63;
        *reinterpret_cast<uint4*>(&Ksw[k*QS_W + (d>>1)]) =
            *reinterpret_cast<const uint4*>(kfp + i);
    }
    for (int i = t*8; i < D_*L_; i += 2048) {
        int d = i >> 7, k = i & 127;
        *reinterpret_cast<uint4*>(&Vtw[d*VS_W + (k>>1)]) =
            *reinterpret_cast<const uint4*>(vtp + i);
    }

    const uint32_t kBase = (uint32_t)__cvta_generic_to_shared(Ksw);
    const uint32_t vBase = (uint32_t)__cvta_generic_to_shared(Vtw);
    const uint32_t qBase = (uint32_t)__cvta_generic_to_shared(Qsw);

    const int lane15 = lane & 15;
    const int lanehi = lane >> 4;
    const int bsel = lane >> 3;
    const int qrow = warp*16;

    const uint32_t qOff = ((qrow + lane15)*QS_W + lanehi*4)*4;
    uint32_t kOff[8];
    #pragma unroll
    for (int pr = 0; pr < 8; pr++) {
        int krow = pr*16 + (bsel>>1)*8 + (lane & 7);
        kOff[pr] = (krow*QS_W + (bsel & 1)*4)*4;
    }
    uint32_t vOff[4];
    #pragma unroll
    for (int pr = 0; pr < 4; pr++) {
        int drow = pr*16 + (bsel>>1)*8 + (lane & 7);
        vOff[pr] = (drow*VS_W + (bsel & 1)*4)*4;
    }

    const float scale = 0.125f;

    for (int qi = 0; qi < 2; qi++) {
        const int qb = qb2*2 + qi;
        if (qi) __syncthreads();     // all reads of previous Q tile done
        {
            long base = ((long)b*N_ + qb*128) * C_ + h*D_;
            for (int i = t*8; i < 128*64; i += 2048) {
                int q = i >> 6, d = i & 63;
                *reinterpret_cast<uint4*>(&Qsw[q*QS_W + (d>>1)]) =
                    *reinterpret_cast<const uint4*>(Q + base + (long)q*C_ + d);
            }
        }
        __syncthreads();

        // --- S = Q K^T ---
        float accS[16][4];
        #pragma unroll
        for (int nt = 0; nt < 16; nt++)
            #pragma unroll
            for (int r = 0; r < 4; r++) accS[nt][r] = 0.f;

        #pragma unroll
        for (int ks = 0; ks < 4; ks++) {
            const uint32_t kwB = ks * 32;
            uint32_t a0, a1, a2, a3;
            ldsm4(a0, a1, a2, a3, qBase + qOff + kwB);
            #pragma unroll
            for (int pr = 0; pr < 8; pr++) {
                uint32_t b00, b01, b10, b11;
                ldsm4(b00, b01, b10, b11, kBase + kOff[pr] + kwB);
                mma_f16(accS[pr*2  ], a0, a1, a2, a3, b00, b01);
                mma_f16(accS[pr*2+1], a0, a1, a2, a3, b10, b11);
            }
        }

        // --- softmax over 128 keys ---
        float m0 = -1e30f, m1 = -1e30f;
        #pragma unroll
        for (int nt = 0; nt < 16; nt++) {
            accS[nt][0] *= scale; accS[nt][1] *= scale;
            accS[nt][2] *= scale; accS[nt][3] *= scale;
            m0 = fmaxf(m0, fmaxf(accS[nt][0], accS[nt][1]));
            m1 = fmaxf(m1, fmaxf(accS[nt][2], accS[nt][3]));
        }
        m0 = fmaxf(m0, __shfl_xor_sync(0xffffffff, m0, 1));
        m0 = fmaxf(m0, __shfl_xor_sync(0xffffffff, m0, 2));
        m1 = fmaxf(m1, __shfl_xor_sync(0xffffffff, m1, 1));
        m1 = fmaxf(m1, __shfl_xor_sync(0xffffffff, m1, 2));

        float l0 = 0.f, l1 = 0.f;
        #pragma unroll
        for (int nt = 0; nt < 16; nt++) {
            accS[nt][0] = __expf(accS[nt][0] - m0);
            accS[nt][1] = __expf(accS[nt][1] - m0);
            accS[nt][2] = __expf(accS[nt][2] - m1);
            accS[nt][3] = __expf(accS[nt][3] - m1);
            l0 += accS[nt][0] + accS[nt][1];
            l1 += accS[nt][2] + accS[nt][3];
        }
        l0 += __shfl_xor_sync(0xffffffff, l0, 1);
        l0 += __shfl_xor_sync(0xffffffff, l0, 2);
        l1 += __shfl_xor_sync(0xffffffff, l1, 1);
        l1 += __shfl_xor_sync(0xffffffff, l1, 2);
        float rl0 = 1.f / l0, rl1 = 1.f / l1;

        // --- pack normalized P into PV A-fragments (register-resident) ---
        uint32_t pfrag[8][4];
        #pragma unroll
        for (int ks = 0; ks < 8; ks++) {
            __half2 f0 = __float22half2_rn(
                make_float2(accS[2*ks  ][0]*rl0, accS[2*ks  ][1]*rl0));
            __half2 f1 = __float22half2_rn(
                make_float2(accS[2*ks  ][2]*rl1, accS[2*ks  ][3]*rl1));
            __half2 f2 = __float22half2_rn(
                make_float2(accS[2*ks+1][0]*rl0, accS[2*ks+1][1]*rl0));
            __half2 f3 = __float22half2_rn(
                make_float2(accS[2*ks+1][2]*rl1, accS[2*ks+1][3]*rl1));
            pfrag[ks][0] = *reinterpret_cast<uint32_t*>(&f0);
            pfrag[ks][1] = *reinterpret_cast<uint32_t*>(&f1);
            pfrag[ks][2] = *reinterpret_cast<uint32_t*>(&f2);
            pfrag[ks][3] = *reinterpret_cast<uint32_t*>(&f3);
        }

        // --- O = P V ---
        float accO[8][4];
        #pragma unroll
        for (int nt = 0; nt < 8; nt++)
            #pragma unroll
            for (int r = 0; r < 4; r++) accO[nt][r] = 0.f;

        #pragma unroll
        for (int ks = 0; ks < 8; ks++) {
            const uint32_t kwB = ks * 32;
            #pragma unroll
            for (int pr = 0; pr < 4; pr++) {
                uint32_t b00, b01, b10, b11;
                ldsm4(b00, b01, b10, b11, vBase + vOff[pr] + kwB);
                mma_f16(accO[pr*2  ], pfrag[ks][0], pfrag[ks][1],
                        pfrag[ks][2], pfrag[ks][3], b00, b01);
                mma_f16(accO[pr*2+1], pfrag[ks][0], pfrag[ks][1],
                        pfrag[ks][2], pfrag[ks][3], b10, b11);
            }
        }

        long row0 = (long)b*N_ + qb*128 + qrow + group;
        #pragma unroll
        for (int nt = 0; nt < 8; nt++) {
            int col = h*D_ + nt*8 + tid4*2;
            __half2 h0 = __float22half2_rn(make_float2(accO[nt][0], accO[nt][1]));
            __half2 h1 = __float22half2_rn(make_float2(accO[nt][2], accO[nt][3]));
            *reinterpret_cast<__half2*>(O + row0*C_ + col) = h0;
            *reinterpret_cast<__half2*>(O + (row0+8)*C_ + col) = h1;
        }
    }
}

// ---------------------------------------------------------------------------
extern "C" void kernel_launch(void* const* d_in, const int* in_sizes, int n_in,
                              void* d_out, int out_size)
{
    const float* x      = (const float*)d_in[0];
    const float* Wqkv   = (const float*)d_in[1];
    const float* bqkv   = (const float*)d_in[2];
    const float* E_k    = (const float*)d_in[3];
    const float* E_v    = (const float*)d_in[4];
    const float* Wproj  = (const float*)d_in[5];
    const float* bproj  = (const float*)d_in[6];
    const float* k_bank = (const float*)d_in[7];
    const float* v_bank = (const float*)d_in[8];

    __half *xh, *Wqt, *Wpt, *Qh, *xph, *KVh, *kfh, *vth, *ao;
    cudaGetSymbolAddress((void**)&xh,  g_xh);
    cudaGetSymbolAddress((void**)&Wqt, g_Wqt);
    cudaGetSymbolAddress((void**)&Wpt, g_Wpt);
    cudaGetSymbolAddress((void**)&Qh,  g_Qh);
    cudaGetSymbolAddress((void**)&xph, g_xph);
    cudaGetSymbolAddress((void**)&KVh, g_KVh);
    cudaGetSymbolAddress((void**)&kfh, g_kfh);
    cudaGetSymbolAddress((void**)&vth, g_vth);
    cudaGetSymbolAddress((void**)&ao,  g_ao);

    cudaFuncSetAttribute(attn_tc,
                         cudaFuncAttributeMaxDynamicSharedMemorySize, ATTN_SMEM);

    // streams/events (host objects only; leaked by design)
    cudaStream_t s2;
    cudaStreamCreateWithFlags(&s2, cudaStreamNonBlocking);
    cudaEvent_t e0, eW, e2;
    cudaEventCreateWithFlags(&e0, cudaEventDisableTiming);
    cudaEventCreateWithFlags(&eW, cudaEventDisableTiming);
    cudaEventCreateWithFlags(&e2, cudaEventDisableTiming);

    // fork s2
    cudaEventRecord(e0, 0);
    cudaStreamWaitEvent(s2, e0, 0);

    // s2: transposes -> pooled tokens -> KV projection -> compress
    f2h_T<<<dim3(3*C_/32, C_/32), dim3(32, 8), 0, s2>>>(Wqkv, Wqt, C_, 3*C_);
    f2h_T<<<dim3(C_/32, C_/32), dim3(32, 8), 0, s2>>>(Wproj, Wpt, C_, C_);
    cudaEventRecord(eW, s2);
    pool_kernel<<<(B_*L_*C_/4 + 255)/256, 256, 0, s2>>>(x, xph);
    hgemm<<<dim3(2*C_/128, B_*L_/128), 256, 0, s2>>>(
        xph, Wqt + (long)C_*C_, bqkv + C_, KVh, C_, C_, C_, 2*C_, 1);
    kvcompress<<<dim3(2, H_, B_), 128, 0, s2>>>(
        KVh, E_k, E_v, k_bank, v_bank, kfh, vth);
    cudaEventRecord(e2, s2);

    // main: x -> fp16
    f2h4<<<B_*N_*C_/4/(256*4), 256>>>(x, xh);

    // main: Q projection (needs Wqt)
    cudaStreamWaitEvent(0, eW, 0);
    hgemm<<<dim3(C_/128, B_*N_/128), 256>>>(xh, Wqt, bqkv, Qh,
                                            C_, C_, C_, C_, 1);

    // join: attention needs kfh/vth
    cudaStreamWaitEvent(0, e2, 0);
    attn_tc<<<dim3(N_/256, H_, B_), 256, ATTN_SMEM>>>(Qh, kfh, vth, ao);

    // out = ao @ Wproj + bproj -> fp32
    hgemm<<<dim3(C_/128, B_*N_/128), 256>>>(ao, Wpt, bproj, (float*)d_out,
                                            C_, C_, C_, C_, 0);
}